// round 12
// baseline (speedup 1.0000x reference)
#include <cuda_runtime.h>
#include <cuda_bf16.h>
#include <math.h>
#include <stdint.h>

#define Nn   4
#define CIN  1024
#define CB   256
#define Hh   56
#define Ww   56
#define HW   3136
#define KT   9
#define KD   (CB * KT)   // 2304

// Scratch (device globals: allocation-free rule)
__device__ float g_r  [Nn * CB * HW];     // conv1 output (relu)
__device__ float g_off[Nn * 2 * KT * HW]; // offset conv output
__device__ float g_r2 [Nn * CB * HW];     // deform conv output (relu)
__device__ __nv_bfloat16 g_w2h[CB * KD];  // w2 split hi, [o][tap*256+c]
__device__ __nv_bfloat16 g_w2l[CB * KD];  // w2 split lo
__device__ __nv_bfloat16 g_w1h[CB * CIN]; // w1 split hi [256][1024]
__device__ __nv_bfloat16 g_w1l[CB * CIN];
__device__ __nv_bfloat16 g_w3h[CIN * CB]; // w3 split hi [1024][256]
__device__ __nv_bfloat16 g_w3l[CIN * CB];

// ---------------------------------------------------------------------------
// helpers
// ---------------------------------------------------------------------------
__device__ __forceinline__ void split2(float x, float y, uint32_t& hi, uint32_t& lo) {
    __nv_bfloat16 xh = __float2bfloat16(x);
    __nv_bfloat16 yh = __float2bfloat16(y);
    __nv_bfloat16 xl = __float2bfloat16(x - __bfloat162float(xh));
    __nv_bfloat16 yl = __float2bfloat16(y - __bfloat162float(yh));
    hi = ((uint32_t)__bfloat16_as_ushort(yh) << 16) | __bfloat16_as_ushort(xh);
    lo = ((uint32_t)__bfloat16_as_ushort(yl) << 16) | __bfloat16_as_ushort(xl);
}

__device__ __forceinline__ void mma16816(float* c, const uint32_t* a, const uint32_t* b) {
    asm volatile(
        "mma.sync.aligned.m16n8k16.row.col.f32.bf16.bf16.f32 "
        "{%0,%1,%2,%3}, {%4,%5,%6,%7}, {%8,%9}, {%0,%1,%2,%3};"
        : "+f"(c[0]), "+f"(c[1]), "+f"(c[2]), "+f"(c[3])
        : "r"(a[0]), "r"(a[1]), "r"(a[2]), "r"(a[3]), "r"(b[0]), "r"(b[1]));
}

__device__ __forceinline__ void ldsm_x4(uint32_t* r, uint32_t addr) {
    asm volatile("ldmatrix.sync.aligned.m8n8.x4.shared.b16 {%0,%1,%2,%3}, [%4];"
                 : "=r"(r[0]), "=r"(r[1]), "=r"(r[2]), "=r"(r[3]) : "r"(addr));
}
__device__ __forceinline__ void ldsm_x2(uint32_t* r, uint32_t addr) {
    asm volatile("ldmatrix.sync.aligned.m8n8.x2.shared.b16 {%0,%1}, [%2];"
                 : "=r"(r[0]), "=r"(r[1]) : "r"(addr));
}
template <int P>
__device__ __forceinline__ uint32_t a_addr(const __nv_bfloat16 (*S)[P], int mb, int ks, int ln) {
    int row = mb + (ln & 7) + ((ln >> 3) & 1) * 8;
    int col = ks + (ln >> 4) * 8;
    return (uint32_t)__cvta_generic_to_shared(&S[row][col]);
}
template <int P>
__device__ __forceinline__ uint32_t b_addr(const __nv_bfloat16 (*S)[P], int nb, int ks, int ln) {
    int l = ln & 15;
    int row = nb + (l & 7);
    int col = ks + ((l >> 3) & 1) * 8;
    return (uint32_t)__cvta_generic_to_shared(&S[row][col]);
}
__device__ __forceinline__ void cp16(uint32_t saddr, const void* g) {
    asm volatile("cp.async.ca.shared.global [%0], [%1], 16;"
                 :: "r"(saddr), "l"(g) : "memory");
}
#define CP_COMMIT() asm volatile("cp.async.commit_group;" ::: "memory")
#define CP_WAIT0()  asm volatile("cp.async.wait_group 0;" ::: "memory")
#define CP_WAIT1()  asm volatile("cp.async.wait_group 1;" ::: "memory")

// ---------------------------------------------------------------------------
// weight prep: fp32 -> bf16 hi/lo
// ---------------------------------------------------------------------------
__global__ void prep_w2_kernel(const float* __restrict__ w2) {
    int i = blockIdx.x * 256 + threadIdx.x;
    if (i < CB * KD) {
        int o = i / KD;
        int k = i % KD;
        int tap = k >> 8;
        int c   = k & 255;
        float v = w2[(o * CB + c) * KT + tap];
        __nv_bfloat16 h = __float2bfloat16(v);
        g_w2h[i] = h;
        g_w2l[i] = __float2bfloat16(v - __bfloat162float(h));
    }
}
__global__ void prep_w_kernel(const float* __restrict__ w,
                              __nv_bfloat16* __restrict__ oh,
                              __nv_bfloat16* __restrict__ ol, int total) {
    int i = blockIdx.x * 256 + threadIdx.x;
    if (i < total) {
        float v = w[i];
        __nv_bfloat16 h = __float2bfloat16(v);
        oh[i] = h;
        ol[i] = __float2bfloat16(v - __bfloat162float(h));
    }
}

// ===========================================================================
// Tensor-core GEMM for 1x1 convs (R11-proven, unchanged).
// ===========================================================================
#define GKP 72
#define G_AS_BYTES (128 * GKP * 2)
#define G_STAGE    (2 * G_AS_BYTES)
#define G_B_OFF    (2 * G_STAGE)
#define G_BS_BYTES (64 * GKP * 2)
#define GSM_BYTES  (G_B_OFF + 2 * G_BS_BYTES)

__global__ __launch_bounds__(256) void gemm_tc_kernel(
        const __nv_bfloat16* __restrict__ Ah,
        const __nv_bfloat16* __restrict__ Al,
        const float* __restrict__ Bx,
        const float* __restrict__ bias, const float* __restrict__ resid,
        float* __restrict__ C, int M, int Kd) {
    extern __shared__ char gsm[];
    typedef __nv_bfloat16 (*tile_t)[GKP];
    tile_t Bs_h = (tile_t)(gsm + G_B_OFF);
    tile_t Bs_l = (tile_t)(gsm + G_B_OFF + G_BS_BYTES);

    const int n  = blockIdx.z;
    const int m0 = blockIdx.y * 128;
    const int p0 = blockIdx.x * 64;
    const int tid = threadIdx.x;
    const int wid = tid >> 5;
    const int lid = tid & 31;
    const int q = lid >> 2;
    const int r = lid & 3;
    const int wm = wid & 3;
    const int wn = wid >> 2;
    const float* Bn = Bx + (size_t)n * Kd * HW;

    const int b_px = (tid & 15) * 4;
    const int b_kp = (tid >> 4) * 2;

    float acc[2][4][4] = {};
    const int KC = Kd >> 6;

#define STAGE_A(s_, k0_) do {                                                  \
    tile_t _ah = (tile_t)(gsm + (s_) * G_STAGE);                               \
    tile_t _al = (tile_t)(gsm + (s_) * G_STAGE + G_AS_BYTES);                  \
    _Pragma("unroll")                                                          \
    for (int pass = 0; pass < 4; ++pass) {                                     \
        int id  = tid + pass * 256;                                            \
        int row = id >> 3;                                                     \
        int col = (id & 7) * 8;                                                \
        size_t goff = (size_t)(m0 + row) * Kd + (k0_) + col;                   \
        cp16((uint32_t)__cvta_generic_to_shared(&_ah[row][col]), Ah + goff);   \
        cp16((uint32_t)__cvta_generic_to_shared(&_al[row][col]), Al + goff);   \
    }                                                                          \
    CP_COMMIT();                                                               \
} while (0)

    float4 vk[2][2];
#define LOAD_B(k0_) do {                                                       \
    _Pragma("unroll")                                                          \
    for (int p = 0; p < 2; ++p) {                                              \
        const float* gB = Bn + (size_t)((k0_) + b_kp + p * 32) * HW + p0 + b_px; \
        vk[p][0] = *(const float4*)gB;                                         \
        vk[p][1] = *(const float4*)(gB + HW);                                  \
    }                                                                          \
} while (0)

#define STORE_B() do {                                                         \
    _Pragma("unroll")                                                          \
    for (int p = 0; p < 2; ++p) {                                              \
        int kk = b_kp + p * 32;                                                \
        float a0[4] = {vk[p][0].x, vk[p][0].y, vk[p][0].z, vk[p][0].w};        \
        float a1[4] = {vk[p][1].x, vk[p][1].y, vk[p][1].z, vk[p][1].w};        \
        _Pragma("unroll")                                                      \
        for (int j = 0; j < 4; ++j) {                                          \
            uint32_t hi, lo;                                                   \
            split2(a0[j], a1[j], hi, lo);                                      \
            *(uint32_t*)&Bs_h[b_px + j][kk] = hi;                              \
            *(uint32_t*)&Bs_l[b_px + j][kk] = lo;                              \
        }                                                                      \
    }                                                                          \
} while (0)

    STAGE_A(0, 0);
    LOAD_B(0);

    for (int kc = 0; kc < KC; ++kc) {
        const int s = kc & 1;
        __syncthreads();
        STORE_B();
        if (kc + 1 < KC) {
            STAGE_A(s ^ 1, (kc + 1) << 6);
            LOAD_B((kc + 1) << 6);
            CP_WAIT1();
        } else {
            CP_WAIT0();
        }
        __syncthreads();

        tile_t ash = (tile_t)(gsm + s * G_STAGE);
        tile_t asl = (tile_t)(gsm + s * G_STAGE + G_AS_BYTES);
#pragma unroll
        for (int ks = 0; ks < 64; ks += 16) {
            uint32_t bh[4][2], bl[4][2];
#pragma unroll
            for (int nf = 0; nf < 4; ++nf) {
                int nb = wn * 32 + nf * 8;
                ldsm_x2(bh[nf], b_addr(Bs_h, nb, ks, lid));
                ldsm_x2(bl[nf], b_addr(Bs_l, nb, ks, lid));
            }
#pragma unroll
            for (int mf = 0; mf < 2; ++mf) {
                int mb = wm * 32 + mf * 16;
                uint32_t ah[4], al[4];
                ldsm_x4(ah, a_addr(ash, mb, ks, lid));
                ldsm_x4(al, a_addr(asl, mb, ks, lid));
#pragma unroll
                for (int nf = 0; nf < 4; ++nf) {
                    mma16816(acc[mf][nf], ah, bh[nf]);
                    mma16816(acc[mf][nf], ah, bl[nf]);
                    mma16816(acc[mf][nf], al, bh[nf]);
                }
            }
        }
    }

#pragma unroll
    for (int mf = 0; mf < 2; ++mf) {
#pragma unroll
        for (int half = 0; half < 2; ++half) {
            int mm = m0 + wm * 32 + mf * 16 + q + half * 8;
            float bb = bias[mm];
#pragma unroll
            for (int nf = 0; nf < 4; ++nf) {
                int px = p0 + wn * 32 + nf * 8 + 2 * r;
                float c0 = acc[mf][nf][half * 2 + 0];
                float c1 = acc[mf][nf][half * 2 + 1];
                size_t base = ((size_t)n * M + mm) * HW + px;
                if (resid) {
                    float2 rv = *(const float2*)(resid + base);
                    c0 += rv.x;
                    c1 += rv.y;
                }
                float2 o;
                o.x = fmaxf(c0 + bb, 0.f);
                o.y = fmaxf(c1 + bb, 0.f);
                *(float2*)(C + base) = o;
            }
        }
    }
}

// ---------------------------------------------------------------------------
// Offset conv: 3x3 SAME, CB=256 -> 18 ch. 32 px/block (R9 version).
// ---------------------------------------------------------------------------
__global__ __launch_bounds__(256) void offset_conv_kernel(
        const float* __restrict__ w_off, const float* __restrict__ b_off) {
    __shared__ float red[8][32][18];
    const int n  = blockIdx.y;
    const int p0 = blockIdx.x * 32;
    const int tid = threadIdx.x;
    const int g  = tid >> 5;
    const int lx = tid & 31;

    float acc[18];
#pragma unroll
    for (int oc = 0; oc < 18; ++oc) acc[oc] = 0.f;

    const int p = p0 + lx;
    const int h = p / Ww, w = p % Ww;

    for (int ci = g; ci < CB; ci += 8) {
        const float* rb = g_r + ((size_t)n * CB + ci) * HW;
        float v[9];
#pragma unroll
        for (int t = 0; t < 9; ++t) {
            int y = h + t / 3 - 1;
            int x = w + t % 3 - 1;
            v[t] = (y >= 0 && y < Hh && x >= 0 && x < Ww) ? __ldg(rb + y * Ww + x) : 0.f;
        }
        const float* wb = w_off + ci * 9;
#pragma unroll
        for (int oc = 0; oc < 18; ++oc) {
#pragma unroll
            for (int t = 0; t < 9; ++t)
                acc[oc] += __ldg(wb + oc * (CB * 9) + t) * v[t];
        }
    }

#pragma unroll
    for (int oc = 0; oc < 18; ++oc)
        red[g][lx][oc] = acc[oc];
    __syncthreads();

    for (int i = tid; i < 32 * 18; i += 256) {
        int ps = i / 18, oc = i % 18;
        float s = b_off[oc];
#pragma unroll
        for (int g2 = 0; g2 < 8; ++g2) s += red[g2][ps][oc];
        g_off[((size_t)n * 18 + oc) * HW + p0 + ps] = s;
    }
}

// ===========================================================================
// Deformable 3x3 conv on tensor cores — SINGLE block per pixel tile computes
// ALL 256 output channels (M=256), eliminating the duplicated gather that
// the 2-block-m-split version did. 512 threads = 16 warps (8m x 2n).
// k = tap*256 + c; 36 chunks of 64 k.
// ===========================================================================
#define DPITCH 72
#define DSM_AS_H 0
#define DSM_AS_L 36864
#define DSM_BS_H 73728
#define DSM_BS_L 82944
#define DSM_BYTES 92160

__global__ __launch_bounds__(512, 1) void deform_mma_kernel(const float* __restrict__ b2) {
    extern __shared__ char dsm[];
    typedef __nv_bfloat16 (*tile_t)[DPITCH];
    tile_t As_h = (tile_t)(dsm + DSM_AS_H);
    tile_t As_l = (tile_t)(dsm + DSM_AS_L);
    tile_t Bs_h = (tile_t)(dsm + DSM_BS_H);
    tile_t Bs_l = (tile_t)(dsm + DSM_BS_L);

    const int pb = blockIdx.x * 64;
    const int n  = blockIdx.z;
    const int tid = threadIdx.x;
    const int wid = tid >> 5;
    const int lid = tid & 31;
    const int q = lid >> 2;
    const int r = lid & 3;
    const int wm = wid & 7;     // 8 m-warps x 32 rows
    const int wn = wid >> 3;    // 2 n-warps x 32 px

    const int gpx = tid & 63;   // pixel
    const int gg  = tid >> 6;   // 0..7 -> 8 channels each
    const int gcl = gg * 8;

    const float* fbase = g_r + (size_t)n * CB * HW;
    const float* offb  = g_off + (size_t)n * 18 * HW + pb + gpx;
    const int gh = (pb + gpx) / Ww;
    const int gw = (pb + gpx) % Ww;

    float acc[2][4][4] = {};

    int   idx0, idx1, idx2, idx3;
    float wt0, wt1, wt2, wt3;
#define BILIN(tap_) do {                                                       \
    float dy = offb[(size_t)((tap_) * 2 + 0) * HW];                            \
    float dx = offb[(size_t)((tap_) * 2 + 1) * HW];                            \
    float ys = (float)(gh + (tap_) / 3 - 1) + dy;                              \
    float xs = (float)(gw + (tap_) % 3 - 1) + dx;                              \
    float y0f = floorf(ys), x0f = floorf(xs);                                  \
    float wy1 = ys - y0f, wy0 = 1.f - wy1;                                     \
    float wx1 = xs - x0f, wx0 = 1.f - wx1;                                     \
    int y0 = (int)y0f, x0 = (int)x0f;                                          \
    int y1 = y0 + 1, x1 = x0 + 1;                                              \
    bool vy0 = (y0 >= 0) && (y0 < Hh);                                         \
    bool vy1 = (y1 >= 0) && (y1 < Hh);                                         \
    bool vx0 = (x0 >= 0) && (x0 < Ww);                                         \
    bool vx1 = (x1 >= 0) && (x1 < Ww);                                         \
    int yc0 = min(max(y0, 0), Hh - 1), yc1 = min(max(y1, 0), Hh - 1);          \
    int xc0 = min(max(x0, 0), Ww - 1), xc1 = min(max(x1, 0), Ww - 1);          \
    idx0 = yc0 * Ww + xc0;  wt0 = (vy0 && vx0) ? wy0 * wx0 : 0.f;              \
    idx1 = yc0 * Ww + xc1;  wt1 = (vy0 && vx1) ? wy0 * wx1 : 0.f;              \
    idx2 = yc1 * Ww + xc0;  wt2 = (vy1 && vx0) ? wy1 * wx0 : 0.f;              \
    idx3 = yc1 * Ww + xc1;  wt3 = (vy1 && vx1) ? wy1 * wx1 : 0.f;              \
} while (0)

    float v[8];
#define GATHER(c0_) do {                                                       \
    _Pragma("unroll")                                                          \
    for (int j = 0; j < 8; ++j) {                                              \
        const float* f = fbase + (size_t)((c0_) + gcl + j) * HW;               \
        v[j] = wt0 * __ldg(f + idx0) + wt1 * __ldg(f + idx1)                   \
             + wt2 * __ldg(f + idx2) + wt3 * __ldg(f + idx3);                  \
    }                                                                          \
} while (0)

    BILIN(0);
    GATHER(0);
    int tap_cur = 0;

    for (int ch = 0; ch < 36; ++ch) {
        const int tap = ch >> 2;
        const int k0  = tap * 256 + (ch & 3) * 64;
        __syncthreads();  // previous MMA done with smem

        // stage weights (256 rows x 64 cols, h+l) via cp.async
#pragma unroll
        for (int pass = 0; pass < 4; ++pass) {
            int id   = tid + pass * 512;     // 0..2047
            int row  = id >> 3;              // 0..255
            int col  = (id & 7) * 8;
            size_t goff = (size_t)row * KD + k0 + col;
            cp16((uint32_t)__cvta_generic_to_shared(&As_h[row][col]), g_w2h + goff);
            cp16((uint32_t)__cvta_generic_to_shared(&As_l[row][col]), g_w2l + goff);
        }
        CP_COMMIT();

        // store gathered values -> Bs (split bf16 hi/lo), 8 ch per thread
        {
            uint4 h0, l0;
            split2(v[0], v[1], h0.x, l0.x);
            split2(v[2], v[3], h0.y, l0.y);
            split2(v[4], v[5], h0.z, l0.z);
            split2(v[6], v[7], h0.w, l0.w);
            *(uint4*)&Bs_h[gpx][gcl] = h0;
            *(uint4*)&Bs_l[gpx][gcl] = l0;
        }

        // prefetch next chunk's gather (overlaps cp.async + MMA)
        if (ch + 1 < 36) {
            int ntap = (ch + 1) >> 2;
            if (ntap != tap_cur) {
                BILIN(ntap);
                tap_cur = ntap;
            }
            GATHER(((ch + 1) & 3) * 64);
        }

        CP_WAIT0();
        __syncthreads();

        // MMA: 4 k16 steps over the 64-k chunk
#pragma unroll
        for (int ks = 0; ks < 64; ks += 16) {
            uint32_t bh[4][2], bl[4][2];
#pragma unroll
            for (int nf = 0; nf < 4; ++nf) {
                int nb = wn * 32 + nf * 8;
                ldsm_x2(bh[nf], b_addr(Bs_h, nb, ks, lid));
                ldsm_x2(bl[nf], b_addr(Bs_l, nb, ks, lid));
            }
#pragma unroll
            for (int mf = 0; mf < 2; ++mf) {
                int mb = wm * 32 + mf * 16;
                uint32_t ah[4], al[4];
                ldsm_x4(ah, a_addr(As_h, mb, ks, lid));
                ldsm_x4(al, a_addr(As_l, mb, ks, lid));
#pragma unroll
                for (int nf = 0; nf < 4; ++nf) {
                    mma16816(acc[mf][nf], ah, bh[nf]);
                    mma16816(acc[mf][nf], ah, bl[nf]);
                    mma16816(acc[mf][nf], al, bh[nf]);
                }
            }
        }
    }

    // epilogue: bias + relu -> g_r2
#pragma unroll
    for (int mf = 0; mf < 2; ++mf) {
#pragma unroll
        for (int half = 0; half < 2; ++half) {
            int o = wm * 32 + mf * 16 + q + half * 8;
            float bb = b2[o];
            float* orow = g_r2 + ((size_t)n * CB + o) * HW + pb;
#pragma unroll
            for (int nf = 0; nf < 4; ++nf) {
                int px = wn * 32 + nf * 8 + 2 * r;
                float2 ov;
                ov.x = fmaxf(acc[mf][nf][half * 2 + 0] + bb, 0.f);
                ov.y = fmaxf(acc[mf][nf][half * 2 + 1] + bb, 0.f);
                *(float2*)(orow + px) = ov;
            }
        }
    }
}

// ---------------------------------------------------------------------------
extern "C" void kernel_launch(void* const* d_in, const int* in_sizes, int n_in,
                              void* d_out, int out_size) {
    const float* x     = (const float*)d_in[0];
    const float* w1    = (const float*)d_in[1];
    const float* b1    = (const float*)d_in[2];
    const float* w_off = (const float*)d_in[3];
    const float* b_off = (const float*)d_in[4];
    const float* w2    = (const float*)d_in[5];
    const float* b2    = (const float*)d_in[6];
    const float* w3    = (const float*)d_in[7];
    const float* b3    = (const float*)d_in[8];
    float* out = (float*)d_out;

    float *r_ptr, *r2_ptr;
    cudaGetSymbolAddress((void**)&r_ptr, g_r);
    cudaGetSymbolAddress((void**)&r2_ptr, g_r2);
    __nv_bfloat16 *w1h, *w1l, *w3h, *w3l;
    cudaGetSymbolAddress((void**)&w1h, g_w1h);
    cudaGetSymbolAddress((void**)&w1l, g_w1l);
    cudaGetSymbolAddress((void**)&w3h, g_w3h);
    cudaGetSymbolAddress((void**)&w3l, g_w3l);

    cudaFuncSetAttribute(deform_mma_kernel,
                         cudaFuncAttributeMaxDynamicSharedMemorySize, DSM_BYTES);
    cudaFuncSetAttribute(gemm_tc_kernel,
                         cudaFuncAttributeMaxDynamicSharedMemorySize, GSM_BYTES);

    // weight preps
    prep_w2_kernel<<<(CB * KD + 255) / 256, 256>>>(w2);
    prep_w_kernel<<<(CB * CIN + 255) / 256, 256>>>(w1, w1h, w1l, CB * CIN);
    prep_w_kernel<<<(CIN * CB + 255) / 256, 256>>>(w3, w3h, w3l, CIN * CB);

    // conv1: 1024 -> 256, relu
    gemm_tc_kernel<<<dim3(HW / 64, CB / 128, Nn), 256, GSM_BYTES>>>(
        w1h, w1l, x, b1, nullptr, r_ptr, CB, CIN);

    // offset conv 3x3: 256 -> 18
    offset_conv_kernel<<<dim3(HW / 32, Nn), 256>>>(w_off, b_off);

    // deformable conv 3x3: 256 -> 256, relu (single-block M=256, no dup gather)
    deform_mma_kernel<<<dim3(HW / 64, 1, Nn), 512, DSM_BYTES>>>(b2);

    // conv3: 256 -> 1024 + x residual, relu
    gemm_tc_kernel<<<dim3(HW / 64, CIN / 128, Nn), 256, GSM_BYTES>>>(
        w3h, w3l, r2_ptr, b3, x, out, CIN, CB);
}

// round 13
// speedup vs baseline: 1.1123x; 1.1123x over previous
#include <cuda_runtime.h>
#include <cuda_bf16.h>
#include <math.h>
#include <stdint.h>

#define Nn   4
#define CIN  1024
#define CB   256
#define Hh   56
#define Ww   56
#define HW   3136
#define KT   9
#define KD   (CB * KT)   // 2304

// Scratch (device globals: allocation-free rule)
__device__ float g_r  [Nn * CB * HW];     // conv1 output (relu)
__device__ float g_off[Nn * 2 * KT * HW]; // offset conv output
__device__ float g_r2 [Nn * CB * HW];     // deform conv output (relu)
__device__ __nv_bfloat16 g_w2h[CB * KD];  // w2 split hi, [o][tap*256+c]
__device__ __nv_bfloat16 g_w2l[CB * KD];  // w2 split lo
__device__ __nv_bfloat16 g_w1h[CB * CIN]; // w1 split hi [256][1024]
__device__ __nv_bfloat16 g_w1l[CB * CIN];
__device__ __nv_bfloat16 g_w3h[CIN * CB]; // w3 split hi [1024][256]
__device__ __nv_bfloat16 g_w3l[CIN * CB];

// ---------------------------------------------------------------------------
// helpers
// ---------------------------------------------------------------------------
__device__ __forceinline__ void split2(float x, float y, uint32_t& hi, uint32_t& lo) {
    __nv_bfloat16 xh = __float2bfloat16(x);
    __nv_bfloat16 yh = __float2bfloat16(y);
    __nv_bfloat16 xl = __float2bfloat16(x - __bfloat162float(xh));
    __nv_bfloat16 yl = __float2bfloat16(y - __bfloat162float(yh));
    hi = ((uint32_t)__bfloat16_as_ushort(yh) << 16) | __bfloat16_as_ushort(xh);
    lo = ((uint32_t)__bfloat16_as_ushort(yl) << 16) | __bfloat16_as_ushort(xl);
}

__device__ __forceinline__ void mma16816(float* c, const uint32_t* a, const uint32_t* b) {
    asm volatile(
        "mma.sync.aligned.m16n8k16.row.col.f32.bf16.bf16.f32 "
        "{%0,%1,%2,%3}, {%4,%5,%6,%7}, {%8,%9}, {%0,%1,%2,%3};"
        : "+f"(c[0]), "+f"(c[1]), "+f"(c[2]), "+f"(c[3])
        : "r"(a[0]), "r"(a[1]), "r"(a[2]), "r"(a[3]), "r"(b[0]), "r"(b[1]));
}

__device__ __forceinline__ void ldsm_x4(uint32_t* r, uint32_t addr) {
    asm volatile("ldmatrix.sync.aligned.m8n8.x4.shared.b16 {%0,%1,%2,%3}, [%4];"
                 : "=r"(r[0]), "=r"(r[1]), "=r"(r[2]), "=r"(r[3]) : "r"(addr));
}
__device__ __forceinline__ void ldsm_x2(uint32_t* r, uint32_t addr) {
    asm volatile("ldmatrix.sync.aligned.m8n8.x2.shared.b16 {%0,%1}, [%2];"
                 : "=r"(r[0]), "=r"(r[1]) : "r"(addr));
}
template <int P>
__device__ __forceinline__ uint32_t a_addr(const __nv_bfloat16 (*S)[P], int mb, int ks, int ln) {
    int row = mb + (ln & 7) + ((ln >> 3) & 1) * 8;
    int col = ks + (ln >> 4) * 8;
    return (uint32_t)__cvta_generic_to_shared(&S[row][col]);
}
template <int P>
__device__ __forceinline__ uint32_t b_addr(const __nv_bfloat16 (*S)[P], int nb, int ks, int ln) {
    int l = ln & 15;
    int row = nb + (l & 7);
    int col = ks + ((l >> 3) & 1) * 8;
    return (uint32_t)__cvta_generic_to_shared(&S[row][col]);
}
__device__ __forceinline__ void cp16(uint32_t saddr, const void* g) {
    asm volatile("cp.async.ca.shared.global [%0], [%1], 16;"
                 :: "r"(saddr), "l"(g) : "memory");
}
#define CP_COMMIT() asm volatile("cp.async.commit_group;" ::: "memory")
#define CP_WAIT0()  asm volatile("cp.async.wait_group 0;" ::: "memory")
#define CP_WAIT1()  asm volatile("cp.async.wait_group 1;" ::: "memory")

// ---------------------------------------------------------------------------
// weight prep: fp32 -> bf16 hi/lo
// ---------------------------------------------------------------------------
__global__ void prep_w2_kernel(const float* __restrict__ w2) {
    int i = blockIdx.x * 256 + threadIdx.x;
    if (i < CB * KD) {
        int o = i / KD;
        int k = i % KD;
        int tap = k >> 8;
        int c   = k & 255;
        float v = w2[(o * CB + c) * KT + tap];
        __nv_bfloat16 h = __float2bfloat16(v);
        g_w2h[i] = h;
        g_w2l[i] = __float2bfloat16(v - __bfloat162float(h));
    }
}
__global__ void prep_w_kernel(const float* __restrict__ w,
                              __nv_bfloat16* __restrict__ oh,
                              __nv_bfloat16* __restrict__ ol, int total) {
    int i = blockIdx.x * 256 + threadIdx.x;
    if (i < total) {
        float v = w[i];
        __nv_bfloat16 h = __float2bfloat16(v);
        oh[i] = h;
        ol[i] = __float2bfloat16(v - __bfloat162float(h));
    }
}

// ===========================================================================
// Tensor-core GEMM for 1x1 convs (R11-proven, unchanged).
// ===========================================================================
#define GKP 72
#define G_AS_BYTES (128 * GKP * 2)
#define G_STAGE    (2 * G_AS_BYTES)
#define G_B_OFF    (2 * G_STAGE)
#define G_BS_BYTES (64 * GKP * 2)
#define GSM_BYTES  (G_B_OFF + 2 * G_BS_BYTES)

__global__ __launch_bounds__(256) void gemm_tc_kernel(
        const __nv_bfloat16* __restrict__ Ah,
        const __nv_bfloat16* __restrict__ Al,
        const float* __restrict__ Bx,
        const float* __restrict__ bias, const float* __restrict__ resid,
        float* __restrict__ C, int M, int Kd) {
    extern __shared__ char gsm[];
    typedef __nv_bfloat16 (*tile_t)[GKP];
    tile_t Bs_h = (tile_t)(gsm + G_B_OFF);
    tile_t Bs_l = (tile_t)(gsm + G_B_OFF + G_BS_BYTES);

    const int n  = blockIdx.z;
    const int m0 = blockIdx.y * 128;
    const int p0 = blockIdx.x * 64;
    const int tid = threadIdx.x;
    const int wid = tid >> 5;
    const int lid = tid & 31;
    const int q = lid >> 2;
    const int r = lid & 3;
    const int wm = wid & 3;
    const int wn = wid >> 2;
    const float* Bn = Bx + (size_t)n * Kd * HW;

    const int b_px = (tid & 15) * 4;
    const int b_kp = (tid >> 4) * 2;

    float acc[2][4][4] = {};
    const int KC = Kd >> 6;

#define STAGE_A(s_, k0_) do {                                                  \
    tile_t _ah = (tile_t)(gsm + (s_) * G_STAGE);                               \
    tile_t _al = (tile_t)(gsm + (s_) * G_STAGE + G_AS_BYTES);                  \
    _Pragma("unroll")                                                          \
    for (int pass = 0; pass < 4; ++pass) {                                     \
        int id  = tid + pass * 256;                                            \
        int row = id >> 3;                                                     \
        int col = (id & 7) * 8;                                                \
        size_t goff = (size_t)(m0 + row) * Kd + (k0_) + col;                   \
        cp16((uint32_t)__cvta_generic_to_shared(&_ah[row][col]), Ah + goff);   \
        cp16((uint32_t)__cvta_generic_to_shared(&_al[row][col]), Al + goff);   \
    }                                                                          \
    CP_COMMIT();                                                               \
} while (0)

    float4 vk[2][2];
#define LOAD_B(k0_) do {                                                       \
    _Pragma("unroll")                                                          \
    for (int p = 0; p < 2; ++p) {                                              \
        const float* gB = Bn + (size_t)((k0_) + b_kp + p * 32) * HW + p0 + b_px; \
        vk[p][0] = *(const float4*)gB;                                         \
        vk[p][1] = *(const float4*)(gB + HW);                                  \
    }                                                                          \
} while (0)

#define STORE_B() do {                                                         \
    _Pragma("unroll")                                                          \
    for (int p = 0; p < 2; ++p) {                                              \
        int kk = b_kp + p * 32;                                                \
        float a0[4] = {vk[p][0].x, vk[p][0].y, vk[p][0].z, vk[p][0].w};        \
        float a1[4] = {vk[p][1].x, vk[p][1].y, vk[p][1].z, vk[p][1].w};        \
        _Pragma("unroll")                                                      \
        for (int j = 0; j < 4; ++j) {                                          \
            uint32_t hi, lo;                                                   \
            split2(a0[j], a1[j], hi, lo);                                      \
            *(uint32_t*)&Bs_h[b_px + j][kk] = hi;                              \
            *(uint32_t*)&Bs_l[b_px + j][kk] = lo;                              \
        }                                                                      \
    }                                                                          \
} while (0)

    STAGE_A(0, 0);
    LOAD_B(0);

    for (int kc = 0; kc < KC; ++kc) {
        const int s = kc & 1;
        __syncthreads();
        STORE_B();
        if (kc + 1 < KC) {
            STAGE_A(s ^ 1, (kc + 1) << 6);
            LOAD_B((kc + 1) << 6);
            CP_WAIT1();
        } else {
            CP_WAIT0();
        }
        __syncthreads();

        tile_t ash = (tile_t)(gsm + s * G_STAGE);
        tile_t asl = (tile_t)(gsm + s * G_STAGE + G_AS_BYTES);
#pragma unroll
        for (int ks = 0; ks < 64; ks += 16) {
            uint32_t bh[4][2], bl[4][2];
#pragma unroll
            for (int nf = 0; nf < 4; ++nf) {
                int nb = wn * 32 + nf * 8;
                ldsm_x2(bh[nf], b_addr(Bs_h, nb, ks, lid));
                ldsm_x2(bl[nf], b_addr(Bs_l, nb, ks, lid));
            }
#pragma unroll
            for (int mf = 0; mf < 2; ++mf) {
                int mb = wm * 32 + mf * 16;
                uint32_t ah[4], al[4];
                ldsm_x4(ah, a_addr(ash, mb, ks, lid));
                ldsm_x4(al, a_addr(asl, mb, ks, lid));
#pragma unroll
                for (int nf = 0; nf < 4; ++nf) {
                    mma16816(acc[mf][nf], ah, bh[nf]);
                    mma16816(acc[mf][nf], ah, bl[nf]);
                    mma16816(acc[mf][nf], al, bh[nf]);
                }
            }
        }
    }

#pragma unroll
    for (int mf = 0; mf < 2; ++mf) {
#pragma unroll
        for (int half = 0; half < 2; ++half) {
            int mm = m0 + wm * 32 + mf * 16 + q + half * 8;
            float bb = bias[mm];
#pragma unroll
            for (int nf = 0; nf < 4; ++nf) {
                int px = p0 + wn * 32 + nf * 8 + 2 * r;
                float c0 = acc[mf][nf][half * 2 + 0];
                float c1 = acc[mf][nf][half * 2 + 1];
                size_t base = ((size_t)n * M + mm) * HW + px;
                if (resid) {
                    float2 rv = *(const float2*)(resid + base);
                    c0 += rv.x;
                    c1 += rv.y;
                }
                float2 o;
                o.x = fmaxf(c0 + bb, 0.f);
                o.y = fmaxf(c1 + bb, 0.f);
                *(float2*)(C + base) = o;
            }
        }
    }
}

// ---------------------------------------------------------------------------
// Offset conv: 3x3 SAME, CB=256 -> 18 ch. 32 px/block (R9 version).
// ---------------------------------------------------------------------------
__global__ __launch_bounds__(256) void offset_conv_kernel(
        const float* __restrict__ w_off, const float* __restrict__ b_off) {
    __shared__ float red[8][32][18];
    const int n  = blockIdx.y;
    const int p0 = blockIdx.x * 32;
    const int tid = threadIdx.x;
    const int g  = tid >> 5;
    const int lx = tid & 31;

    float acc[18];
#pragma unroll
    for (int oc = 0; oc < 18; ++oc) acc[oc] = 0.f;

    const int p = p0 + lx;
    const int h = p / Ww, w = p % Ww;

    for (int ci = g; ci < CB; ci += 8) {
        const float* rb = g_r + ((size_t)n * CB + ci) * HW;
        float v[9];
#pragma unroll
        for (int t = 0; t < 9; ++t) {
            int y = h + t / 3 - 1;
            int x = w + t % 3 - 1;
            v[t] = (y >= 0 && y < Hh && x >= 0 && x < Ww) ? __ldg(rb + y * Ww + x) : 0.f;
        }
        const float* wb = w_off + ci * 9;
#pragma unroll
        for (int oc = 0; oc < 18; ++oc) {
#pragma unroll
            for (int t = 0; t < 9; ++t)
                acc[oc] += __ldg(wb + oc * (CB * 9) + t) * v[t];
        }
    }

#pragma unroll
    for (int oc = 0; oc < 18; ++oc)
        red[g][lx][oc] = acc[oc];
    __syncthreads();

    for (int i = tid; i < 32 * 18; i += 256) {
        int ps = i / 18, oc = i % 18;
        float s = b_off[oc];
#pragma unroll
        for (int g2 = 0; g2 < 8; ++g2) s += red[g2][ps][oc];
        g_off[((size_t)n * 18 + oc) * HW + p0 + ps] = s;
    }
}

// ===========================================================================
// Deformable 3x3 conv on tensor cores — 32 px x 256 o per block (gather
// deduped across the full M like R12, but with R11's residency: 256 thr,
// 83 KB smem -> 2 blocks/SM, grid 392).
// 8 warps = 8m x 1n; warp = 32 o x 32 px. k = tap*256 + c; 36 chunks of 64.
// ===========================================================================
#define DPITCH 72
#define DSM_AS_H 0
#define DSM_AS_L 36864
#define DSM_BS_H 73728
#define DSM_BS_L 78336
#define DSM_BYTES 82944

__global__ __launch_bounds__(256, 2) void deform_mma_kernel(const float* __restrict__ b2) {
    extern __shared__ char dsm[];
    typedef __nv_bfloat16 (*tile_t)[DPITCH];
    tile_t As_h = (tile_t)(dsm + DSM_AS_H);
    tile_t As_l = (tile_t)(dsm + DSM_AS_L);
    tile_t Bs_h = (tile_t)(dsm + DSM_BS_H);
    tile_t Bs_l = (tile_t)(dsm + DSM_BS_L);

    const int pb = blockIdx.x * 32;
    const int n  = blockIdx.z;
    const int tid = threadIdx.x;
    const int wid = tid >> 5;    // 0..7 -> m warp (32 o rows each)
    const int lid = tid & 31;
    const int q = lid >> 2;
    const int r = lid & 3;

    const int gpx = tid & 31;    // pixel
    const int gg  = tid >> 5;    // 0..7 -> 8 channels each
    const int gcl = gg * 8;

    const float* fbase = g_r + (size_t)n * CB * HW;
    const float* offb  = g_off + (size_t)n * 18 * HW + pb + gpx;
    const int gh = (pb + gpx) / Ww;
    const int gw = (pb + gpx) % Ww;

    float acc[2][4][4] = {};   // [mf][nf][4]

    int   idx0, idx1, idx2, idx3;
    float wt0, wt1, wt2, wt3;
#define BILIN(tap_) do {                                                       \
    float dy = offb[(size_t)((tap_) * 2 + 0) * HW];                            \
    float dx = offb[(size_t)((tap_) * 2 + 1) * HW];                            \
    float ys = (float)(gh + (tap_) / 3 - 1) + dy;                              \
    float xs = (float)(gw + (tap_) % 3 - 1) + dx;                              \
    float y0f = floorf(ys), x0f = floorf(xs);                                  \
    float wy1 = ys - y0f, wy0 = 1.f - wy1;                                     \
    float wx1 = xs - x0f, wx0 = 1.f - wx1;                                     \
    int y0 = (int)y0f, x0 = (int)x0f;                                          \
    int y1 = y0 + 1, x1 = x0 + 1;                                              \
    bool vy0 = (y0 >= 0) && (y0 < Hh);                                         \
    bool vy1 = (y1 >= 0) && (y1 < Hh);                                         \
    bool vx0 = (x0 >= 0) && (x0 < Ww);                                         \
    bool vx1 = (x1 >= 0) && (x1 < Ww);                                         \
    int yc0 = min(max(y0, 0), Hh - 1), yc1 = min(max(y1, 0), Hh - 1);          \
    int xc0 = min(max(x0, 0), Ww - 1), xc1 = min(max(x1, 0), Ww - 1);          \
    idx0 = yc0 * Ww + xc0;  wt0 = (vy0 && vx0) ? wy0 * wx0 : 0.f;              \
    idx1 = yc0 * Ww + xc1;  wt1 = (vy0 && vx1) ? wy0 * wx1 : 0.f;              \
    idx2 = yc1 * Ww + xc0;  wt2 = (vy1 && vx0) ? wy1 * wx0 : 0.f;              \
    idx3 = yc1 * Ww + xc1;  wt3 = (vy1 && vx1) ? wy1 * wx1 : 0.f;              \
} while (0)

    float v[8];
#define GATHER(c0_) do {                                                       \
    _Pragma("unroll")                                                          \
    for (int j = 0; j < 8; ++j) {                                              \
        const float* f = fbase + (size_t)((c0_) + gcl + j) * HW;               \
        v[j] = wt0 * __ldg(f + idx0) + wt1 * __ldg(f + idx1)                   \
             + wt2 * __ldg(f + idx2) + wt3 * __ldg(f + idx3);                  \
    }                                                                          \
} while (0)

    BILIN(0);
    GATHER(0);
    int tap_cur = 0;

    for (int ch = 0; ch < 36; ++ch) {
        const int tap = ch >> 2;
        const int k0  = tap * 256 + (ch & 3) * 64;
        __syncthreads();  // previous MMA done with smem

        // stage weights (256 rows x 64 cols, h+l) via cp.async
#pragma unroll
        for (int pass = 0; pass < 8; ++pass) {
            int id   = tid + pass * 256;     // 0..2047
            int row  = id >> 3;              // 0..255
            int col  = (id & 7) * 8;
            size_t goff = (size_t)row * KD + k0 + col;
            cp16((uint32_t)__cvta_generic_to_shared(&As_h[row][col]), g_w2h + goff);
            cp16((uint32_t)__cvta_generic_to_shared(&As_l[row][col]), g_w2l + goff);
        }
        CP_COMMIT();

        // store gathered values -> Bs (split bf16 hi/lo), 8 ch per thread
        {
            uint4 h0, l0;
            split2(v[0], v[1], h0.x, l0.x);
            split2(v[2], v[3], h0.y, l0.y);
            split2(v[4], v[5], h0.z, l0.z);
            split2(v[6], v[7], h0.w, l0.w);
            *(uint4*)&Bs_h[gpx][gcl] = h0;
            *(uint4*)&Bs_l[gpx][gcl] = l0;
        }

        // prefetch next chunk's gather (overlaps cp.async + MMA)
        if (ch + 1 < 36) {
            int ntap = (ch + 1) >> 2;
            if (ntap != tap_cur) {
                BILIN(ntap);
                tap_cur = ntap;
            }
            GATHER(((ch + 1) & 3) * 64);
        }

        CP_WAIT0();
        __syncthreads();

        // MMA: 4 k16 steps over the 64-k chunk
#pragma unroll
        for (int ks = 0; ks < 64; ks += 16) {
            uint32_t bh[4][2], bl[4][2];
#pragma unroll
            for (int nf = 0; nf < 4; ++nf) {
                int nb = nf * 8;
                ldsm_x2(bh[nf], b_addr(Bs_h, nb, ks, lid));
                ldsm_x2(bl[nf], b_addr(Bs_l, nb, ks, lid));
            }
#pragma unroll
            for (int mf = 0; mf < 2; ++mf) {
                int mb = wid * 32 + mf * 16;
                uint32_t ah[4], al[4];
                ldsm_x4(ah, a_addr(As_h, mb, ks, lid));
                ldsm_x4(al, a_addr(As_l, mb, ks, lid));
#pragma unroll
                for (int nf = 0; nf < 4; ++nf) {
                    mma16816(acc[mf][nf], ah, bh[nf]);
                    mma16816(acc[mf][nf], ah, bl[nf]);
                    mma16816(acc[mf][nf], al, bh[nf]);
                }
            }
        }
    }

    // epilogue: bias + relu -> g_r2
#pragma unroll
    for (int mf = 0; mf < 2; ++mf) {
#pragma unroll
        for (int half = 0; half < 2; ++half) {
            int o = wid * 32 + mf * 16 + q + half * 8;
            float bb = b2[o];
            float* orow = g_r2 + ((size_t)n * CB + o) * HW + pb;
#pragma unroll
            for (int nf = 0; nf < 4; ++nf) {
                int px = nf * 8 + 2 * r;
                float2 ov;
                ov.x = fmaxf(acc[mf][nf][half * 2 + 0] + bb, 0.f);
                ov.y = fmaxf(acc[mf][nf][half * 2 + 1] + bb, 0.f);
                *(float2*)(orow + px) = ov;
            }
        }
    }
}

// ---------------------------------------------------------------------------
extern "C" void kernel_launch(void* const* d_in, const int* in_sizes, int n_in,
                              void* d_out, int out_size) {
    const float* x     = (const float*)d_in[0];
    const float* w1    = (const float*)d_in[1];
    const float* b1    = (const float*)d_in[2];
    const float* w_off = (const float*)d_in[3];
    const float* b_off = (const float*)d_in[4];
    const float* w2    = (const float*)d_in[5];
    const float* b2    = (const float*)d_in[6];
    const float* w3    = (const float*)d_in[7];
    const float* b3    = (const float*)d_in[8];
    float* out = (float*)d_out;

    float *r_ptr, *r2_ptr;
    cudaGetSymbolAddress((void**)&r_ptr, g_r);
    cudaGetSymbolAddress((void**)&r2_ptr, g_r2);
    __nv_bfloat16 *w1h, *w1l, *w3h, *w3l;
    cudaGetSymbolAddress((void**)&w1h, g_w1h);
    cudaGetSymbolAddress((void**)&w1l, g_w1l);
    cudaGetSymbolAddress((void**)&w3h, g_w3h);
    cudaGetSymbolAddress((void**)&w3l, g_w3l);

    cudaFuncSetAttribute(deform_mma_kernel,
                         cudaFuncAttributeMaxDynamicSharedMemorySize, DSM_BYTES);
    cudaFuncSetAttribute(gemm_tc_kernel,
                         cudaFuncAttributeMaxDynamicSharedMemorySize, GSM_BYTES);

    // weight preps
    prep_w2_kernel<<<(CB * KD + 255) / 256, 256>>>(w2);
    prep_w_kernel<<<(CB * CIN + 255) / 256, 256>>>(w1, w1h, w1l, CB * CIN);
    prep_w_kernel<<<(CIN * CB + 255) / 256, 256>>>(w3, w3h, w3l, CIN * CB);

    // conv1: 1024 -> 256, relu
    gemm_tc_kernel<<<dim3(HW / 64, CB / 128, Nn), 256, GSM_BYTES>>>(
        w1h, w1l, x, b1, nullptr, r_ptr, CB, CIN);

    // offset conv 3x3: 256 -> 18
    offset_conv_kernel<<<dim3(HW / 32, Nn), 256>>>(w_off, b_off);

    // deformable conv 3x3: 256 -> 256, relu (32px x 256o, deduped gather)
    deform_mma_kernel<<<dim3(HW / 32, 1, Nn), 256, DSM_BYTES>>>(b2);

    // conv3: 256 -> 1024 + x residual, relu
    gemm_tc_kernel<<<dim3(HW / 64, CIN / 128, Nn), 256, GSM_BYTES>>>(
        w3h, w3l, r2_ptr, b3, x, out, CIN, CB);
}

// round 14
// speedup vs baseline: 1.1416x; 1.0263x over previous
#include <cuda_runtime.h>
#include <cuda_bf16.h>
#include <math.h>
#include <stdint.h>

#define Nn   4
#define CIN  1024
#define CB   256
#define Hh   56
#define Ww   56
#define HW   3136
#define KT   9
#define KD   (CB * KT)   // 2304

// Scratch (device globals: allocation-free rule)
__device__ float g_r  [Nn * CB * HW];     // conv1 output (relu)
__device__ float g_off[Nn * 2 * KT * HW]; // offset conv output
__device__ __nv_bfloat16 g_r2h[Nn * CB * HW]; // deform out, bf16 hi
__device__ __nv_bfloat16 g_r2l[Nn * CB * HW]; // deform out, bf16 lo
__device__ __nv_bfloat16 g_w2h[CB * KD];  // w2 split hi, [o][tap*256+c]
__device__ __nv_bfloat16 g_w2l[CB * KD];  // w2 split lo
__device__ __nv_bfloat16 g_w1h[CB * CIN]; // w1 split hi [256][1024]
__device__ __nv_bfloat16 g_w1l[CB * CIN];
__device__ __nv_bfloat16 g_w3h[CIN * CB]; // w3 split hi [1024][256]
__device__ __nv_bfloat16 g_w3l[CIN * CB];

// ---------------------------------------------------------------------------
// helpers
// ---------------------------------------------------------------------------
__device__ __forceinline__ void split2(float x, float y, uint32_t& hi, uint32_t& lo) {
    __nv_bfloat16 xh = __float2bfloat16(x);
    __nv_bfloat16 yh = __float2bfloat16(y);
    __nv_bfloat16 xl = __float2bfloat16(x - __bfloat162float(xh));
    __nv_bfloat16 yl = __float2bfloat16(y - __bfloat162float(yh));
    hi = ((uint32_t)__bfloat16_as_ushort(yh) << 16) | __bfloat16_as_ushort(xh);
    lo = ((uint32_t)__bfloat16_as_ushort(yl) << 16) | __bfloat16_as_ushort(xl);
}

__device__ __forceinline__ void mma16816(float* c, const uint32_t* a, const uint32_t* b) {
    asm volatile(
        "mma.sync.aligned.m16n8k16.row.col.f32.bf16.bf16.f32 "
        "{%0,%1,%2,%3}, {%4,%5,%6,%7}, {%8,%9}, {%0,%1,%2,%3};"
        : "+f"(c[0]), "+f"(c[1]), "+f"(c[2]), "+f"(c[3])
        : "r"(a[0]), "r"(a[1]), "r"(a[2]), "r"(a[3]), "r"(b[0]), "r"(b[1]));
}

__device__ __forceinline__ void ldsm_x4(uint32_t* r, uint32_t addr) {
    asm volatile("ldmatrix.sync.aligned.m8n8.x4.shared.b16 {%0,%1,%2,%3}, [%4];"
                 : "=r"(r[0]), "=r"(r[1]), "=r"(r[2]), "=r"(r[3]) : "r"(addr));
}
__device__ __forceinline__ void ldsm_x2(uint32_t* r, uint32_t addr) {
    asm volatile("ldmatrix.sync.aligned.m8n8.x2.shared.b16 {%0,%1}, [%2];"
                 : "=r"(r[0]), "=r"(r[1]) : "r"(addr));
}
__device__ __forceinline__ void ldsm_x2t(uint32_t* r, uint32_t addr) {
    asm volatile("ldmatrix.sync.aligned.m8n8.x2.trans.shared.b16 {%0,%1}, [%2];"
                 : "=r"(r[0]), "=r"(r[1]) : "r"(addr));
}
template <int P>
__device__ __forceinline__ uint32_t a_addr(const __nv_bfloat16 (*S)[P], int mb, int ks, int ln) {
    int row = mb + (ln & 7) + ((ln >> 3) & 1) * 8;
    int col = ks + (ln >> 4) * 8;
    return (uint32_t)__cvta_generic_to_shared(&S[row][col]);
}
template <int P>
__device__ __forceinline__ uint32_t b_addr(const __nv_bfloat16 (*S)[P], int nb, int ks, int ln) {
    int l = ln & 15;
    int row = nb + (l & 7);
    int col = ks + ((l >> 3) & 1) * 8;
    return (uint32_t)__cvta_generic_to_shared(&S[row][col]);
}
// B stored k-major [k][px]; ldsm.trans. lanes 0..15 -> rows ks..ks+15, col nb.
template <int P>
__device__ __forceinline__ uint32_t b_addr_t(const __nv_bfloat16 (*S)[P], int nb, int ks, int ln) {
    int row = ks + (ln & 15);
    return (uint32_t)__cvta_generic_to_shared(&S[row][nb]);
}
__device__ __forceinline__ void cp16(uint32_t saddr, const void* g) {
    asm volatile("cp.async.ca.shared.global [%0], [%1], 16;"
                 :: "r"(saddr), "l"(g) : "memory");
}
#define CP_COMMIT() asm volatile("cp.async.commit_group;" ::: "memory")
#define CP_WAIT0()  asm volatile("cp.async.wait_group 0;" ::: "memory")
#define CP_WAIT1()  asm volatile("cp.async.wait_group 1;" ::: "memory")

// ---------------------------------------------------------------------------
// weight prep: fp32 -> bf16 hi/lo
// ---------------------------------------------------------------------------
__global__ void prep_w2_kernel(const float* __restrict__ w2) {
    int i = blockIdx.x * 256 + threadIdx.x;
    if (i < CB * KD) {
        int o = i / KD;
        int k = i % KD;
        int tap = k >> 8;
        int c   = k & 255;
        float v = w2[(o * CB + c) * KT + tap];
        __nv_bfloat16 h = __float2bfloat16(v);
        g_w2h[i] = h;
        g_w2l[i] = __float2bfloat16(v - __bfloat162float(h));
    }
}
__global__ void prep_w_kernel(const float* __restrict__ w,
                              __nv_bfloat16* __restrict__ oh,
                              __nv_bfloat16* __restrict__ ol, int total) {
    int i = blockIdx.x * 256 + threadIdx.x;
    if (i < total) {
        float v = w[i];
        __nv_bfloat16 h = __float2bfloat16(v);
        oh[i] = h;
        ol[i] = __float2bfloat16(v - __bfloat162float(h));
    }
}

// ===========================================================================
// Tensor-core GEMM for conv1 (R11-proven, unchanged): A pre-split bf16 via
// cp.async double buffer; B fp32 loaded + split in-kernel.
// ===========================================================================
#define GKP 72
#define G_AS_BYTES (128 * GKP * 2)
#define G_STAGE    (2 * G_AS_BYTES)
#define G_B_OFF    (2 * G_STAGE)
#define G_BS_BYTES (64 * GKP * 2)
#define GSM_BYTES  (G_B_OFF + 2 * G_BS_BYTES)

__global__ __launch_bounds__(256) void gemm_tc_kernel(
        const __nv_bfloat16* __restrict__ Ah,
        const __nv_bfloat16* __restrict__ Al,
        const float* __restrict__ Bx,
        const float* __restrict__ bias, const float* __restrict__ resid,
        float* __restrict__ C, int M, int Kd) {
    extern __shared__ char gsm[];
    typedef __nv_bfloat16 (*tile_t)[GKP];
    tile_t Bs_h = (tile_t)(gsm + G_B_OFF);
    tile_t Bs_l = (tile_t)(gsm + G_B_OFF + G_BS_BYTES);

    const int n  = blockIdx.z;
    const int m0 = blockIdx.y * 128;
    const int p0 = blockIdx.x * 64;
    const int tid = threadIdx.x;
    const int wid = tid >> 5;
    const int lid = tid & 31;
    const int q = lid >> 2;
    const int r = lid & 3;
    const int wm = wid & 3;
    const int wn = wid >> 2;
    const float* Bn = Bx + (size_t)n * Kd * HW;

    const int b_px = (tid & 15) * 4;
    const int b_kp = (tid >> 4) * 2;

    float acc[2][4][4] = {};
    const int KC = Kd >> 6;

#define STAGE_A(s_, k0_) do {                                                  \
    tile_t _ah = (tile_t)(gsm + (s_) * G_STAGE);                               \
    tile_t _al = (tile_t)(gsm + (s_) * G_STAGE + G_AS_BYTES);                  \
    _Pragma("unroll")                                                          \
    for (int pass = 0; pass < 4; ++pass) {                                     \
        int id  = tid + pass * 256;                                            \
        int row = id >> 3;                                                     \
        int col = (id & 7) * 8;                                                \
        size_t goff = (size_t)(m0 + row) * Kd + (k0_) + col;                   \
        cp16((uint32_t)__cvta_generic_to_shared(&_ah[row][col]), Ah + goff);   \
        cp16((uint32_t)__cvta_generic_to_shared(&_al[row][col]), Al + goff);   \
    }                                                                          \
    CP_COMMIT();                                                               \
} while (0)

    float4 vk[2][2];
#define LOAD_B(k0_) do {                                                       \
    _Pragma("unroll")                                                          \
    for (int p = 0; p < 2; ++p) {                                              \
        const float* gB = Bn + (size_t)((k0_) + b_kp + p * 32) * HW + p0 + b_px; \
        vk[p][0] = *(const float4*)gB;                                         \
        vk[p][1] = *(const float4*)(gB + HW);                                  \
    }                                                                          \
} while (0)

#define STORE_B() do {                                                         \
    _Pragma("unroll")                                                          \
    for (int p = 0; p < 2; ++p) {                                              \
        int kk = b_kp + p * 32;                                                \
        float a0[4] = {vk[p][0].x, vk[p][0].y, vk[p][0].z, vk[p][0].w};        \
        float a1[4] = {vk[p][1].x, vk[p][1].y, vk[p][1].z, vk[p][1].w};        \
        _Pragma("unroll")                                                      \
        for (int j = 0; j < 4; ++j) {                                          \
            uint32_t hi, lo;                                                   \
            split2(a0[j], a1[j], hi, lo);                                      \
            *(uint32_t*)&Bs_h[b_px + j][kk] = hi;                              \
            *(uint32_t*)&Bs_l[b_px + j][kk] = lo;                              \
        }                                                                      \
    }                                                                          \
} while (0)

    STAGE_A(0, 0);
    LOAD_B(0);

    for (int kc = 0; kc < KC; ++kc) {
        const int s = kc & 1;
        __syncthreads();
        STORE_B();
        if (kc + 1 < KC) {
            STAGE_A(s ^ 1, (kc + 1) << 6);
            LOAD_B((kc + 1) << 6);
            CP_WAIT1();
        } else {
            CP_WAIT0();
        }
        __syncthreads();

        tile_t ash = (tile_t)(gsm + s * G_STAGE);
        tile_t asl = (tile_t)(gsm + s * G_STAGE + G_AS_BYTES);
#pragma unroll
        for (int ks = 0; ks < 64; ks += 16) {
            uint32_t bh[4][2], bl[4][2];
#pragma unroll
            for (int nf = 0; nf < 4; ++nf) {
                int nb = wn * 32 + nf * 8;
                ldsm_x2(bh[nf], b_addr(Bs_h, nb, ks, lid));
                ldsm_x2(bl[nf], b_addr(Bs_l, nb, ks, lid));
            }
#pragma unroll
            for (int mf = 0; mf < 2; ++mf) {
                int mb = wm * 32 + mf * 16;
                uint32_t ah[4], al[4];
                ldsm_x4(ah, a_addr(ash, mb, ks, lid));
                ldsm_x4(al, a_addr(asl, mb, ks, lid));
#pragma unroll
                for (int nf = 0; nf < 4; ++nf) {
                    mma16816(acc[mf][nf], ah, bh[nf]);
                    mma16816(acc[mf][nf], ah, bl[nf]);
                    mma16816(acc[mf][nf], al, bh[nf]);
                }
            }
        }
    }

#pragma unroll
    for (int mf = 0; mf < 2; ++mf) {
#pragma unroll
        for (int half = 0; half < 2; ++half) {
            int mm = m0 + wm * 32 + mf * 16 + q + half * 8;
            float bb = bias[mm];
#pragma unroll
            for (int nf = 0; nf < 4; ++nf) {
                int px = p0 + wn * 32 + nf * 8 + 2 * r;
                float c0 = acc[mf][nf][half * 2 + 0];
                float c1 = acc[mf][nf][half * 2 + 1];
                size_t base = ((size_t)n * M + mm) * HW + px;
                if (resid) {
                    float2 rv = *(const float2*)(resid + base);
                    c0 += rv.x;
                    c1 += rv.y;
                }
                float2 o;
                o.x = fmaxf(c0 + bb, 0.f);
                o.y = fmaxf(c1 + bb, 0.f);
                *(float2*)(C + base) = o;
            }
        }
    }
}

// ===========================================================================
// conv3 GEMM: A AND B pre-split bf16, both cp.async double-buffered one
// chunk ahead (wait free). B tiles k-major [k][px], ldmatrix.trans frags.
// No conversion math, no register prefetch, no STS phase.
// ===========================================================================
#define BB_A_TILE (128 * GKP * 2)        // 18432
#define BB_A_STAGE (2 * BB_A_TILE)       // 36864 (h+l)
#define BB_B_OFF   (2 * BB_A_STAGE)      // 73728
#define BB_B_TILE  (64 * GKP * 2)        // 9216
#define BB_B_STAGE (2 * BB_B_TILE)       // 18432 (h+l)
#define BBSM_BYTES (BB_B_OFF + 2 * BB_B_STAGE)  // 110592

__global__ __launch_bounds__(256) void gemm_bf16b_kernel(
        const __nv_bfloat16* __restrict__ Ah,
        const __nv_bfloat16* __restrict__ Al,
        const __nv_bfloat16* __restrict__ Bh,
        const __nv_bfloat16* __restrict__ Bl,
        const float* __restrict__ bias, const float* __restrict__ resid,
        float* __restrict__ C, int M, int Kd) {
    extern __shared__ char gsm[];
    typedef __nv_bfloat16 (*tile_t)[GKP];

    const int n  = blockIdx.z;
    const int m0 = blockIdx.y * 128;
    const int p0 = blockIdx.x * 64;
    const int tid = threadIdx.x;
    const int wid = tid >> 5;
    const int lid = tid & 31;
    const int q = lid >> 2;
    const int r = lid & 3;
    const int wm = wid & 3;
    const int wn = wid >> 2;

    float acc[2][4][4] = {};
    const int KC = Kd >> 6;   // 4 for Kd=256

#define STAGE_AB(s_, k0_) do {                                                 \
    tile_t _ah = (tile_t)(gsm + (s_) * BB_A_STAGE);                            \
    tile_t _al = (tile_t)(gsm + (s_) * BB_A_STAGE + BB_A_TILE);                \
    tile_t _bh = (tile_t)(gsm + BB_B_OFF + (s_) * BB_B_STAGE);                 \
    tile_t _bl = (tile_t)(gsm + BB_B_OFF + (s_) * BB_B_STAGE + BB_B_TILE);     \
    _Pragma("unroll")                                                          \
    for (int pass = 0; pass < 4; ++pass) {                                     \
        int id  = tid + pass * 256;                                            \
        int row = id >> 3;                                                     \
        int col = (id & 7) * 8;                                                \
        size_t goff = (size_t)(m0 + row) * Kd + (k0_) + col;                   \
        cp16((uint32_t)__cvta_generic_to_shared(&_ah[row][col]), Ah + goff);   \
        cp16((uint32_t)__cvta_generic_to_shared(&_al[row][col]), Al + goff);   \
    }                                                                          \
    _Pragma("unroll")                                                          \
    for (int pass = 0; pass < 2; ++pass) {                                     \
        int id  = tid + pass * 256;   /* 0..511: 64 rows x 8 px-chunks */      \
        int row = id >> 3;                                                     \
        int col = (id & 7) * 8;                                                \
        size_t goff = ((size_t)n * Kd + (k0_) + row) * HW + p0 + col;          \
        cp16((uint32_t)__cvta_generic_to_shared(&_bh[row][col]), Bh + goff);   \
        cp16((uint32_t)__cvta_generic_to_shared(&_bl[row][col]), Bl + goff);   \
    }                                                                          \
    CP_COMMIT();                                                               \
} while (0)

    STAGE_AB(0, 0);

    for (int kc = 0; kc < KC; ++kc) {
        const int s = kc & 1;
        __syncthreads();           // MMA(kc-1) done reading stage s^1
        if (kc + 1 < KC) {
            STAGE_AB(s ^ 1, (kc + 1) << 6);
            CP_WAIT1();            // stage s complete (committed last iter)
        } else {
            CP_WAIT0();
        }
        __syncthreads();

        tile_t ash = (tile_t)(gsm + s * BB_A_STAGE);
        tile_t asl = (tile_t)(gsm + s * BB_A_STAGE + BB_A_TILE);
        tile_t bsh = (tile_t)(gsm + BB_B_OFF + s * BB_B_STAGE);
        tile_t bsl = (tile_t)(gsm + BB_B_OFF + s * BB_B_STAGE + BB_B_TILE);
#pragma unroll
        for (int ks = 0; ks < 64; ks += 16) {
            uint32_t bh[4][2], bl[4][2];
#pragma unroll
            for (int nf = 0; nf < 4; ++nf) {
                int nb = wn * 32 + nf * 8;
                ldsm_x2t(bh[nf], b_addr_t(bsh, nb, ks, lid));
                ldsm_x2t(bl[nf], b_addr_t(bsl, nb, ks, lid));
            }
#pragma unroll
            for (int mf = 0; mf < 2; ++mf) {
                int mb = wm * 32 + mf * 16;
                uint32_t ah[4], al[4];
                ldsm_x4(ah, a_addr(ash, mb, ks, lid));
                ldsm_x4(al, a_addr(asl, mb, ks, lid));
#pragma unroll
                for (int nf = 0; nf < 4; ++nf) {
                    mma16816(acc[mf][nf], ah, bh[nf]);
                    mma16816(acc[mf][nf], ah, bl[nf]);
                    mma16816(acc[mf][nf], al, bh[nf]);
                }
            }
        }
    }

#pragma unroll
    for (int mf = 0; mf < 2; ++mf) {
#pragma unroll
        for (int half = 0; half < 2; ++half) {
            int mm = m0 + wm * 32 + mf * 16 + q + half * 8;
            float bb = bias[mm];
#pragma unroll
            for (int nf = 0; nf < 4; ++nf) {
                int px = p0 + wn * 32 + nf * 8 + 2 * r;
                float c0 = acc[mf][nf][half * 2 + 0];
                float c1 = acc[mf][nf][half * 2 + 1];
                size_t base = ((size_t)n * M + mm) * HW + px;
                float2 rv = *(const float2*)(resid + base);
                c0 += rv.x;
                c1 += rv.y;
                float2 o;
                o.x = fmaxf(c0 + bb, 0.f);
                o.y = fmaxf(c1 + bb, 0.f);
                *(float2*)(C + base) = o;
            }
        }
    }
}

// ---------------------------------------------------------------------------
// Offset conv: 3x3 SAME, CB=256 -> 18 ch. 32 px/block (R9 version).
// ---------------------------------------------------------------------------
__global__ __launch_bounds__(256) void offset_conv_kernel(
        const float* __restrict__ w_off, const float* __restrict__ b_off) {
    __shared__ float red[8][32][18];
    const int n  = blockIdx.y;
    const int p0 = blockIdx.x * 32;
    const int tid = threadIdx.x;
    const int g  = tid >> 5;
    const int lx = tid & 31;

    float acc[18];
#pragma unroll
    for (int oc = 0; oc < 18; ++oc) acc[oc] = 0.f;

    const int p = p0 + lx;
    const int h = p / Ww, w = p % Ww;

    for (int ci = g; ci < CB; ci += 8) {
        const float* rb = g_r + ((size_t)n * CB + ci) * HW;
        float v[9];
#pragma unroll
        for (int t = 0; t < 9; ++t) {
            int y = h + t / 3 - 1;
            int x = w + t % 3 - 1;
            v[t] = (y >= 0 && y < Hh && x >= 0 && x < Ww) ? __ldg(rb + y * Ww + x) : 0.f;
        }
        const float* wb = w_off + ci * 9;
#pragma unroll
        for (int oc = 0; oc < 18; ++oc) {
#pragma unroll
            for (int t = 0; t < 9; ++t)
                acc[oc] += __ldg(wb + oc * (CB * 9) + t) * v[t];
        }
    }

#pragma unroll
    for (int oc = 0; oc < 18; ++oc)
        red[g][lx][oc] = acc[oc];
    __syncthreads();

    for (int i = tid; i < 32 * 18; i += 256) {
        int ps = i / 18, oc = i % 18;
        float s = b_off[oc];
#pragma unroll
        for (int g2 = 0; g2 < 8; ++g2) s += red[g2][ps][oc];
        g_off[((size_t)n * 18 + oc) * HW + p0 + ps] = s;
    }
}

// ===========================================================================
// Deformable 3x3 conv on tensor cores (R13-proven structure). Epilogue now
// writes bf16 hi/lo (pre-split for conv3) instead of fp32 — same byte count.
// ===========================================================================
#define DPITCH 72
#define DSM_AS_H 0
#define DSM_AS_L 36864
#define DSM_BS_H 73728
#define DSM_BS_L 78336
#define DSM_BYTES 82944

__global__ __launch_bounds__(256, 2) void deform_mma_kernel(const float* __restrict__ b2) {
    extern __shared__ char dsm[];
    typedef __nv_bfloat16 (*tile_t)[DPITCH];
    tile_t As_h = (tile_t)(dsm + DSM_AS_H);
    tile_t As_l = (tile_t)(dsm + DSM_AS_L);
    tile_t Bs_h = (tile_t)(dsm + DSM_BS_H);
    tile_t Bs_l = (tile_t)(dsm + DSM_BS_L);

    const int pb = blockIdx.x * 32;
    const int n  = blockIdx.z;
    const int tid = threadIdx.x;
    const int wid = tid >> 5;
    const int lid = tid & 31;
    const int q = lid >> 2;
    const int r = lid & 3;

    const int gpx = tid & 31;
    const int gg  = tid >> 5;
    const int gcl = gg * 8;

    const float* fbase = g_r + (size_t)n * CB * HW;
    const float* offb  = g_off + (size_t)n * 18 * HW + pb + gpx;
    const int gh = (pb + gpx) / Ww;
    const int gw = (pb + gpx) % Ww;

    float acc[2][4][4] = {};

    int   idx0, idx1, idx2, idx3;
    float wt0, wt1, wt2, wt3;
#define BILIN(tap_) do {                                                       \
    float dy = offb[(size_t)((tap_) * 2 + 0) * HW];                            \
    float dx = offb[(size_t)((tap_) * 2 + 1) * HW];                            \
    float ys = (float)(gh + (tap_) / 3 - 1) + dy;                              \
    float xs = (float)(gw + (tap_) % 3 - 1) + dx;                              \
    float y0f = floorf(ys), x0f = floorf(xs);                                  \
    float wy1 = ys - y0f, wy0 = 1.f - wy1;                                     \
    float wx1 = xs - x0f, wx0 = 1.f - wx1;                                     \
    int y0 = (int)y0f, x0 = (int)x0f;                                          \
    int y1 = y0 + 1, x1 = x0 + 1;                                              \
    bool vy0 = (y0 >= 0) && (y0 < Hh);                                         \
    bool vy1 = (y1 >= 0) && (y1 < Hh);                                         \
    bool vx0 = (x0 >= 0) && (x0 < Ww);                                         \
    bool vx1 = (x1 >= 0) && (x1 < Ww);                                         \
    int yc0 = min(max(y0, 0), Hh - 1), yc1 = min(max(y1, 0), Hh - 1);          \
    int xc0 = min(max(x0, 0), Ww - 1), xc1 = min(max(x1, 0), Ww - 1);          \
    idx0 = yc0 * Ww + xc0;  wt0 = (vy0 && vx0) ? wy0 * wx0 : 0.f;              \
    idx1 = yc0 * Ww + xc1;  wt1 = (vy0 && vx1) ? wy0 * wx1 : 0.f;              \
    idx2 = yc1 * Ww + xc0;  wt2 = (vy1 && vx0) ? wy1 * wx0 : 0.f;              \
    idx3 = yc1 * Ww + xc1;  wt3 = (vy1 && vx1) ? wy1 * wx1 : 0.f;              \
} while (0)

    float v[8];
#define GATHER(c0_) do {                                                       \
    _Pragma("unroll")                                                          \
    for (int j = 0; j < 8; ++j) {                                              \
        const float* f = fbase + (size_t)((c0_) + gcl + j) * HW;               \
        v[j] = wt0 * __ldg(f + idx0) + wt1 * __ldg(f + idx1)                   \
             + wt2 * __ldg(f + idx2) + wt3 * __ldg(f + idx3);                  \
    }                                                                          \
} while (0)

    BILIN(0);
    GATHER(0);
    int tap_cur = 0;

    for (int ch = 0; ch < 36; ++ch) {
        const int tap = ch >> 2;
        const int k0  = tap * 256 + (ch & 3) * 64;
        __syncthreads();

        // stage weights (256 rows x 64 cols, h+l) via cp.async
#pragma unroll
        for (int pass = 0; pass < 8; ++pass) {
            int id   = tid + pass * 256;
            int row  = id >> 3;
            int col  = (id & 7) * 8;
            size_t goff = (size_t)row * KD + k0 + col;
            cp16((uint32_t)__cvta_generic_to_shared(&As_h[row][col]), g_w2h + goff);
            cp16((uint32_t)__cvta_generic_to_shared(&As_l[row][col]), g_w2l + goff);
        }
        CP_COMMIT();

        // store gathered values -> Bs (split bf16 hi/lo), 8 ch per thread
        {
            uint4 h0, l0;
            split2(v[0], v[1], h0.x, l0.x);
            split2(v[2], v[3], h0.y, l0.y);
            split2(v[4], v[5], h0.z, l0.z);
            split2(v[6], v[7], h0.w, l0.w);
            *(uint4*)&Bs_h[gpx][gcl] = h0;
            *(uint4*)&Bs_l[gpx][gcl] = l0;
        }

        // prefetch next chunk's gather (overlaps cp.async + MMA)
        if (ch + 1 < 36) {
            int ntap = (ch + 1) >> 2;
            if (ntap != tap_cur) {
                BILIN(ntap);
                tap_cur = ntap;
            }
            GATHER(((ch + 1) & 3) * 64);
        }

        CP_WAIT0();
        __syncthreads();

#pragma unroll
        for (int ks = 0; ks < 64; ks += 16) {
            uint32_t bh[4][2], bl[4][2];
#pragma unroll
            for (int nf = 0; nf < 4; ++nf) {
                int nb = nf * 8;
                ldsm_x2(bh[nf], b_addr(Bs_h, nb, ks, lid));
                ldsm_x2(bl[nf], b_addr(Bs_l, nb, ks, lid));
            }
#pragma unroll
            for (int mf = 0; mf < 2; ++mf) {
                int mb = wid * 32 + mf * 16;
                uint32_t ah[4], al[4];
                ldsm_x4(ah, a_addr(As_h, mb, ks, lid));
                ldsm_x4(al, a_addr(As_l, mb, ks, lid));
#pragma unroll
                for (int nf = 0; nf < 4; ++nf) {
                    mma16816(acc[mf][nf], ah, bh[nf]);
                    mma16816(acc[mf][nf], ah, bl[nf]);
                    mma16816(acc[mf][nf], al, bh[nf]);
                }
            }
        }
    }

    // epilogue: bias + relu -> g_r2h/g_r2l (pre-split bf16 for conv3)
#pragma unroll
    for (int mf = 0; mf < 2; ++mf) {
#pragma unroll
        for (int half = 0; half < 2; ++half) {
            int o = wid * 32 + mf * 16 + q + half * 8;
            float bb = b2[o];
            size_t rowoff = ((size_t)n * CB + o) * HW + pb;
#pragma unroll
            for (int nf = 0; nf < 4; ++nf) {
                int px = nf * 8 + 2 * r;
                float c0 = fmaxf(acc[mf][nf][half * 2 + 0] + bb, 0.f);
                float c1 = fmaxf(acc[mf][nf][half * 2 + 1] + bb, 0.f);
                uint32_t hi, lo;
                split2(c0, c1, hi, lo);
                *(uint32_t*)&g_r2h[rowoff + px] = hi;
                *(uint32_t*)&g_r2l[rowoff + px] = lo;
            }
        }
    }
}

// ---------------------------------------------------------------------------
extern "C" void kernel_launch(void* const* d_in, const int* in_sizes, int n_in,
                              void* d_out, int out_size) {
    const float* x     = (const float*)d_in[0];
    const float* w1    = (const float*)d_in[1];
    const float* b1    = (const float*)d_in[2];
    const float* w_off = (const float*)d_in[3];
    const float* b_off = (const float*)d_in[4];
    const float* w2    = (const float*)d_in[5];
    const float* b2    = (const float*)d_in[6];
    const float* w3    = (const float*)d_in[7];
    const float* b3    = (const float*)d_in[8];
    float* out = (float*)d_out;

    float* r_ptr;
    cudaGetSymbolAddress((void**)&r_ptr, g_r);
    __nv_bfloat16 *w1h, *w1l, *w3h, *w3l, *r2h, *r2l;
    cudaGetSymbolAddress((void**)&w1h, g_w1h);
    cudaGetSymbolAddress((void**)&w1l, g_w1l);
    cudaGetSymbolAddress((void**)&w3h, g_w3h);
    cudaGetSymbolAddress((void**)&w3l, g_w3l);
    cudaGetSymbolAddress((void**)&r2h, g_r2h);
    cudaGetSymbolAddress((void**)&r2l, g_r2l);

    cudaFuncSetAttribute(deform_mma_kernel,
                         cudaFuncAttributeMaxDynamicSharedMemorySize, DSM_BYTES);
    cudaFuncSetAttribute(gemm_tc_kernel,
                         cudaFuncAttributeMaxDynamicSharedMemorySize, GSM_BYTES);
    cudaFuncSetAttribute(gemm_bf16b_kernel,
                         cudaFuncAttributeMaxDynamicSharedMemorySize, BBSM_BYTES);

    // weight preps
    prep_w2_kernel<<<(CB * KD + 255) / 256, 256>>>(w2);
    prep_w_kernel<<<(CB * CIN + 255) / 256, 256>>>(w1, w1h, w1l, CB * CIN);
    prep_w_kernel<<<(CIN * CB + 255) / 256, 256>>>(w3, w3h, w3l, CIN * CB);

    // conv1: 1024 -> 256, relu
    gemm_tc_kernel<<<dim3(HW / 64, CB / 128, Nn), 256, GSM_BYTES>>>(
        w1h, w1l, x, b1, nullptr, r_ptr, CB, CIN);

    // offset conv 3x3: 256 -> 18
    offset_conv_kernel<<<dim3(HW / 32, Nn), 256>>>(w_off, b_off);

    // deformable conv 3x3: 256 -> 256, relu (writes pre-split bf16)
    deform_mma_kernel<<<dim3(HW / 32, 1, Nn), 256, DSM_BYTES>>>(b2);

    // conv3: 256 -> 1024 + x residual, relu (all-bf16 GEMM)
    gemm_bf16b_kernel<<<dim3(HW / 64, CIN / 128, Nn), 256, BBSM_BYTES>>>(
        w3h, w3l, r2h, r2l, b3, x, out, CIN, CB);
}

// round 15
// speedup vs baseline: 1.1791x; 1.0329x over previous
#include <cuda_runtime.h>
#include <cuda_bf16.h>
#include <math.h>
#include <stdint.h>

#define Nn   4
#define CIN  1024
#define CB   256
#define Hh   56
#define Ww   56
#define HW   3136
#define KT   9
#define KD   (CB * KT)   // 2304

// Scratch (device globals: allocation-free rule)
__device__ float g_r  [Nn * CB * HW];     // conv1 output (relu)
__device__ float g_off[Nn * 2 * KT * HW]; // offset conv output
__device__ __nv_bfloat16 g_r2h[Nn * CB * HW]; // deform out, bf16 hi
__device__ __nv_bfloat16 g_r2l[Nn * CB * HW]; // deform out, bf16 lo
__device__ __nv_bfloat16 g_w2h[CB * KD];  // w2 split hi, [o][tap*256+c]
__device__ __nv_bfloat16 g_w2l[CB * KD];  // w2 split lo
__device__ __nv_bfloat16 g_w1h[CB * CIN]; // w1 split hi [256][1024]
__device__ __nv_bfloat16 g_w1l[CB * CIN];
__device__ __nv_bfloat16 g_w3h[CIN * CB]; // w3 split hi [1024][256]
__device__ __nv_bfloat16 g_w3l[CIN * CB];

// ---------------------------------------------------------------------------
// helpers
// ---------------------------------------------------------------------------
__device__ __forceinline__ void split2(float x, float y, uint32_t& hi, uint32_t& lo) {
    __nv_bfloat16 xh = __float2bfloat16(x);
    __nv_bfloat16 yh = __float2bfloat16(y);
    __nv_bfloat16 xl = __float2bfloat16(x - __bfloat162float(xh));
    __nv_bfloat16 yl = __float2bfloat16(y - __bfloat162float(yh));
    hi = ((uint32_t)__bfloat16_as_ushort(yh) << 16) | __bfloat16_as_ushort(xh);
    lo = ((uint32_t)__bfloat16_as_ushort(yl) << 16) | __bfloat16_as_ushort(xl);
}

__device__ __forceinline__ void mma16816(float* c, const uint32_t* a, const uint32_t* b) {
    asm volatile(
        "mma.sync.aligned.m16n8k16.row.col.f32.bf16.bf16.f32 "
        "{%0,%1,%2,%3}, {%4,%5,%6,%7}, {%8,%9}, {%0,%1,%2,%3};"
        : "+f"(c[0]), "+f"(c[1]), "+f"(c[2]), "+f"(c[3])
        : "r"(a[0]), "r"(a[1]), "r"(a[2]), "r"(a[3]), "r"(b[0]), "r"(b[1]));
}

__device__ __forceinline__ void ldsm_x4(uint32_t* r, uint32_t addr) {
    asm volatile("ldmatrix.sync.aligned.m8n8.x4.shared.b16 {%0,%1,%2,%3}, [%4];"
                 : "=r"(r[0]), "=r"(r[1]), "=r"(r[2]), "=r"(r[3]) : "r"(addr));
}
__device__ __forceinline__ void ldsm_x2(uint32_t* r, uint32_t addr) {
    asm volatile("ldmatrix.sync.aligned.m8n8.x2.shared.b16 {%0,%1}, [%2];"
                 : "=r"(r[0]), "=r"(r[1]) : "r"(addr));
}
__device__ __forceinline__ void ldsm_x2t(uint32_t* r, uint32_t addr) {
    asm volatile("ldmatrix.sync.aligned.m8n8.x2.trans.shared.b16 {%0,%1}, [%2];"
                 : "=r"(r[0]), "=r"(r[1]) : "r"(addr));
}
template <int P>
__device__ __forceinline__ uint32_t a_addr(const __nv_bfloat16 (*S)[P], int mb, int ks, int ln) {
    int row = mb + (ln & 7) + ((ln >> 3) & 1) * 8;
    int col = ks + (ln >> 4) * 8;
    return (uint32_t)__cvta_generic_to_shared(&S[row][col]);
}
template <int P>
__device__ __forceinline__ uint32_t b_addr(const __nv_bfloat16 (*S)[P], int nb, int ks, int ln) {
    int l = ln & 15;
    int row = nb + (l & 7);
    int col = ks + ((l >> 3) & 1) * 8;
    return (uint32_t)__cvta_generic_to_shared(&S[row][col]);
}
// B stored k-major [k][px]; ldsm.trans. lanes 0..15 -> rows ks..ks+15, col nb.
template <int P>
__device__ __forceinline__ uint32_t b_addr_t(const __nv_bfloat16 (*S)[P], int nb, int ks, int ln) {
    int row = ks + (ln & 15);
    return (uint32_t)__cvta_generic_to_shared(&S[row][nb]);
}
__device__ __forceinline__ void cp16(uint32_t saddr, const void* g) {
    asm volatile("cp.async.ca.shared.global [%0], [%1], 16;"
                 :: "r"(saddr), "l"(g) : "memory");
}
#define CP_COMMIT() asm volatile("cp.async.commit_group;" ::: "memory")
#define CP_WAIT0()  asm volatile("cp.async.wait_group 0;" ::: "memory")
#define CP_WAIT1()  asm volatile("cp.async.wait_group 1;" ::: "memory")

// ---------------------------------------------------------------------------
// weight prep: fp32 -> bf16 hi/lo
// ---------------------------------------------------------------------------
__global__ void prep_w2_kernel(const float* __restrict__ w2) {
    int i = blockIdx.x * 256 + threadIdx.x;
    if (i < CB * KD) {
        int o = i / KD;
        int k = i % KD;
        int tap = k >> 8;
        int c   = k & 255;
        float v = w2[(o * CB + c) * KT + tap];
        __nv_bfloat16 h = __float2bfloat16(v);
        g_w2h[i] = h;
        g_w2l[i] = __float2bfloat16(v - __bfloat162float(h));
    }
}
__global__ void prep_w_kernel(const float* __restrict__ w,
                              __nv_bfloat16* __restrict__ oh,
                              __nv_bfloat16* __restrict__ ol, int total) {
    int i = blockIdx.x * 256 + threadIdx.x;
    if (i < total) {
        float v = w[i];
        __nv_bfloat16 h = __float2bfloat16(v);
        oh[i] = h;
        ol[i] = __float2bfloat16(v - __bfloat162float(h));
    }
}

// ===========================================================================
// Tensor-core GEMM for conv1: A pre-split bf16 via cp.async double buffer;
// B fp32 loaded coalesced, split, stored K-MAJOR (conflict-free STS.64),
// consumed via ldmatrix.trans (mirrors the validated conv3 path).
// ===========================================================================
#define GKP 72
#define G_AS_BYTES (128 * GKP * 2)
#define G_STAGE    (2 * G_AS_BYTES)
#define G_B_OFF    (2 * G_STAGE)
#define G_BS_BYTES (64 * GKP * 2)
#define GSM_BYTES  (G_B_OFF + 2 * G_BS_BYTES)

__global__ __launch_bounds__(256) void gemm_tc_kernel(
        const __nv_bfloat16* __restrict__ Ah,
        const __nv_bfloat16* __restrict__ Al,
        const float* __restrict__ Bx,
        const float* __restrict__ bias, const float* __restrict__ resid,
        float* __restrict__ C, int M, int Kd) {
    extern __shared__ char gsm[];
    typedef __nv_bfloat16 (*tile_t)[GKP];
    tile_t Bs_h = (tile_t)(gsm + G_B_OFF);                 // [64 k][72 px pitch]
    tile_t Bs_l = (tile_t)(gsm + G_B_OFF + G_BS_BYTES);

    const int n  = blockIdx.z;
    const int m0 = blockIdx.y * 128;
    const int p0 = blockIdx.x * 64;
    const int tid = threadIdx.x;
    const int wid = tid >> 5;
    const int lid = tid & 31;
    const int q = lid >> 2;
    const int r = lid & 3;
    const int wm = wid & 3;
    const int wn = wid >> 2;
    const float* Bn = Bx + (size_t)n * Kd * HW;

    const int b_px = (tid & 15) * 4;
    const int b_kp = (tid >> 4) * 2;

    float acc[2][4][4] = {};
    const int KC = Kd >> 6;

#define STAGE_A(s_, k0_) do {                                                  \
    tile_t _ah = (tile_t)(gsm + (s_) * G_STAGE);                               \
    tile_t _al = (tile_t)(gsm + (s_) * G_STAGE + G_AS_BYTES);                  \
    _Pragma("unroll")                                                          \
    for (int pass = 0; pass < 4; ++pass) {                                     \
        int id  = tid + pass * 256;                                            \
        int row = id >> 3;                                                     \
        int col = (id & 7) * 8;                                                \
        size_t goff = (size_t)(m0 + row) * Kd + (k0_) + col;                   \
        cp16((uint32_t)__cvta_generic_to_shared(&_ah[row][col]), Ah + goff);   \
        cp16((uint32_t)__cvta_generic_to_shared(&_al[row][col]), Al + goff);   \
    }                                                                          \
    CP_COMMIT();                                                               \
} while (0)

    float4 vk[2][2];
#define LOAD_B(k0_) do {                                                       \
    _Pragma("unroll")                                                          \
    for (int p = 0; p < 2; ++p) {                                              \
        const float* gB = Bn + (size_t)((k0_) + b_kp + p * 32) * HW + p0 + b_px; \
        vk[p][0] = *(const float4*)gB;                                         \
        vk[p][1] = *(const float4*)(gB + HW);                                  \
    }                                                                          \
} while (0)

    // k-major store: thread writes its 4 px (row-contiguous) for each k row.
#define STORE_B() do {                                                         \
    _Pragma("unroll")                                                          \
    for (int p = 0; p < 2; ++p) {                                              \
        _Pragma("unroll")                                                      \
        for (int rr = 0; rr < 2; ++rr) {                                       \
            float4 vv = vk[p][rr];                                             \
            uint32_t h0, l0, h1, l1;                                           \
            split2(vv.x, vv.y, h0, l0);                                        \
            split2(vv.z, vv.w, h1, l1);                                        \
            int kk = b_kp + p * 32 + rr;                                       \
            *(uint2*)&Bs_h[kk][b_px] = make_uint2(h0, h1);                     \
            *(uint2*)&Bs_l[kk][b_px] = make_uint2(l0, l1);                     \
        }                                                                      \
    }                                                                          \
} while (0)

    STAGE_A(0, 0);
    LOAD_B(0);

    for (int kc = 0; kc < KC; ++kc) {
        const int s = kc & 1;
        __syncthreads();
        STORE_B();
        if (kc + 1 < KC) {
            STAGE_A(s ^ 1, (kc + 1) << 6);
            LOAD_B((kc + 1) << 6);
            CP_WAIT1();
        } else {
            CP_WAIT0();
        }
        __syncthreads();

        tile_t ash = (tile_t)(gsm + s * G_STAGE);
        tile_t asl = (tile_t)(gsm + s * G_STAGE + G_AS_BYTES);
#pragma unroll
        for (int ks = 0; ks < 64; ks += 16) {
            uint32_t bh[4][2], bl[4][2];
#pragma unroll
            for (int nf = 0; nf < 4; ++nf) {
                int nb = wn * 32 + nf * 8;
                ldsm_x2t(bh[nf], b_addr_t(Bs_h, nb, ks, lid));
                ldsm_x2t(bl[nf], b_addr_t(Bs_l, nb, ks, lid));
            }
#pragma unroll
            for (int mf = 0; mf < 2; ++mf) {
                int mb = wm * 32 + mf * 16;
                uint32_t ah[4], al[4];
                ldsm_x4(ah, a_addr(ash, mb, ks, lid));
                ldsm_x4(al, a_addr(asl, mb, ks, lid));
#pragma unroll
                for (int nf = 0; nf < 4; ++nf) {
                    mma16816(acc[mf][nf], ah, bh[nf]);
                    mma16816(acc[mf][nf], ah, bl[nf]);
                    mma16816(acc[mf][nf], al, bh[nf]);
                }
            }
        }
    }

#pragma unroll
    for (int mf = 0; mf < 2; ++mf) {
#pragma unroll
        for (int half = 0; half < 2; ++half) {
            int mm = m0 + wm * 32 + mf * 16 + q + half * 8;
            float bb = bias[mm];
#pragma unroll
            for (int nf = 0; nf < 4; ++nf) {
                int px = p0 + wn * 32 + nf * 8 + 2 * r;
                float c0 = acc[mf][nf][half * 2 + 0];
                float c1 = acc[mf][nf][half * 2 + 1];
                size_t base = ((size_t)n * M + mm) * HW + px;
                if (resid) {
                    float2 rv = *(const float2*)(resid + base);
                    c0 += rv.x;
                    c1 += rv.y;
                }
                float2 o;
                o.x = fmaxf(c0 + bb, 0.f);
                o.y = fmaxf(c1 + bb, 0.f);
                *(float2*)(C + base) = o;
            }
        }
    }
}

// ===========================================================================
// conv3 GEMM: A AND B pre-split bf16 (R14-proven, unchanged).
// ===========================================================================
#define BB_A_TILE (128 * GKP * 2)
#define BB_A_STAGE (2 * BB_A_TILE)
#define BB_B_OFF   (2 * BB_A_STAGE)
#define BB_B_TILE  (64 * GKP * 2)
#define BB_B_STAGE (2 * BB_B_TILE)
#define BBSM_BYTES (BB_B_OFF + 2 * BB_B_STAGE)

__global__ __launch_bounds__(256) void gemm_bf16b_kernel(
        const __nv_bfloat16* __restrict__ Ah,
        const __nv_bfloat16* __restrict__ Al,
        const __nv_bfloat16* __restrict__ Bh,
        const __nv_bfloat16* __restrict__ Bl,
        const float* __restrict__ bias, const float* __restrict__ resid,
        float* __restrict__ C, int M, int Kd) {
    extern __shared__ char gsm[];
    typedef __nv_bfloat16 (*tile_t)[GKP];

    const int n  = blockIdx.z;
    const int m0 = blockIdx.y * 128;
    const int p0 = blockIdx.x * 64;
    const int tid = threadIdx.x;
    const int wid = tid >> 5;
    const int lid = tid & 31;
    const int q = lid >> 2;
    const int r = lid & 3;
    const int wm = wid & 3;
    const int wn = wid >> 2;

    float acc[2][4][4] = {};
    const int KC = Kd >> 6;

#define STAGE_AB(s_, k0_) do {                                                 \
    tile_t _ah = (tile_t)(gsm + (s_) * BB_A_STAGE);                            \
    tile_t _al = (tile_t)(gsm + (s_) * BB_A_STAGE + BB_A_TILE);                \
    tile_t _bh = (tile_t)(gsm + BB_B_OFF + (s_) * BB_B_STAGE);                 \
    tile_t _bl = (tile_t)(gsm + BB_B_OFF + (s_) * BB_B_STAGE + BB_B_TILE);     \
    _Pragma("unroll")                                                          \
    for (int pass = 0; pass < 4; ++pass) {                                     \
        int id  = tid + pass * 256;                                            \
        int row = id >> 3;                                                     \
        int col = (id & 7) * 8;                                                \
        size_t goff = (size_t)(m0 + row) * Kd + (k0_) + col;                   \
        cp16((uint32_t)__cvta_generic_to_shared(&_ah[row][col]), Ah + goff);   \
        cp16((uint32_t)__cvta_generic_to_shared(&_al[row][col]), Al + goff);   \
    }                                                                          \
    _Pragma("unroll")                                                          \
    for (int pass = 0; pass < 2; ++pass) {                                     \
        int id  = tid + pass * 256;                                            \
        int row = id >> 3;                                                     \
        int col = (id & 7) * 8;                                                \
        size_t goff = ((size_t)n * Kd + (k0_) + row) * HW + p0 + col;          \
        cp16((uint32_t)__cvta_generic_to_shared(&_bh[row][col]), Bh + goff);   \
        cp16((uint32_t)__cvta_generic_to_shared(&_bl[row][col]), Bl + goff);   \
    }                                                                          \
    CP_COMMIT();                                                               \
} while (0)

    STAGE_AB(0, 0);

    for (int kc = 0; kc < KC; ++kc) {
        const int s = kc & 1;
        __syncthreads();
        if (kc + 1 < KC) {
            STAGE_AB(s ^ 1, (kc + 1) << 6);
            CP_WAIT1();
        } else {
            CP_WAIT0();
        }
        __syncthreads();

        tile_t ash = (tile_t)(gsm + s * BB_A_STAGE);
        tile_t asl = (tile_t)(gsm + s * BB_A_STAGE + BB_A_TILE);
        tile_t bsh = (tile_t)(gsm + BB_B_OFF + s * BB_B_STAGE);
        tile_t bsl = (tile_t)(gsm + BB_B_OFF + s * BB_B_STAGE + BB_B_TILE);
#pragma unroll
        for (int ks = 0; ks < 64; ks += 16) {
            uint32_t bh[4][2], bl[4][2];
#pragma unroll
            for (int nf = 0; nf < 4; ++nf) {
                int nb = wn * 32 + nf * 8;
                ldsm_x2t(bh[nf], b_addr_t(bsh, nb, ks, lid));
                ldsm_x2t(bl[nf], b_addr_t(bsl, nb, ks, lid));
            }
#pragma unroll
            for (int mf = 0; mf < 2; ++mf) {
                int mb = wm * 32 + mf * 16;
                uint32_t ah[4], al[4];
                ldsm_x4(ah, a_addr(ash, mb, ks, lid));
                ldsm_x4(al, a_addr(asl, mb, ks, lid));
#pragma unroll
                for (int nf = 0; nf < 4; ++nf) {
                    mma16816(acc[mf][nf], ah, bh[nf]);
                    mma16816(acc[mf][nf], ah, bl[nf]);
                    mma16816(acc[mf][nf], al, bh[nf]);
                }
            }
        }
    }

#pragma unroll
    for (int mf = 0; mf < 2; ++mf) {
#pragma unroll
        for (int half = 0; half < 2; ++half) {
            int mm = m0 + wm * 32 + mf * 16 + q + half * 8;
            float bb = bias[mm];
#pragma unroll
            for (int nf = 0; nf < 4; ++nf) {
                int px = p0 + wn * 32 + nf * 8 + 2 * r;
                float c0 = acc[mf][nf][half * 2 + 0];
                float c1 = acc[mf][nf][half * 2 + 1];
                size_t base = ((size_t)n * M + mm) * HW + px;
                float2 rv = *(const float2*)(resid + base);
                c0 += rv.x;
                c1 += rv.y;
                float2 o;
                o.x = fmaxf(c0 + bb, 0.f);
                o.y = fmaxf(c1 + bb, 0.f);
                *(float2*)(C + base) = o;
            }
        }
    }
}

// ---------------------------------------------------------------------------
// Offset conv: 3x3 SAME, CB=256 -> 18 ch. 32 px/block (R9 version).
// ---------------------------------------------------------------------------
__global__ __launch_bounds__(256) void offset_conv_kernel(
        const float* __restrict__ w_off, const float* __restrict__ b_off) {
    __shared__ float red[8][32][18];
    const int n  = blockIdx.y;
    const int p0 = blockIdx.x * 32;
    const int tid = threadIdx.x;
    const int g  = tid >> 5;
    const int lx = tid & 31;

    float acc[18];
#pragma unroll
    for (int oc = 0; oc < 18; ++oc) acc[oc] = 0.f;

    const int p = p0 + lx;
    const int h = p / Ww, w = p % Ww;

    for (int ci = g; ci < CB; ci += 8) {
        const float* rb = g_r + ((size_t)n * CB + ci) * HW;
        float v[9];
#pragma unroll
        for (int t = 0; t < 9; ++t) {
            int y = h + t / 3 - 1;
            int x = w + t % 3 - 1;
            v[t] = (y >= 0 && y < Hh && x >= 0 && x < Ww) ? __ldg(rb + y * Ww + x) : 0.f;
        }
        const float* wb = w_off + ci * 9;
#pragma unroll
        for (int oc = 0; oc < 18; ++oc) {
#pragma unroll
            for (int t = 0; t < 9; ++t)
                acc[oc] += __ldg(wb + oc * (CB * 9) + t) * v[t];
        }
    }

#pragma unroll
    for (int oc = 0; oc < 18; ++oc)
        red[g][lx][oc] = acc[oc];
    __syncthreads();

    for (int i = tid; i < 32 * 18; i += 256) {
        int ps = i / 18, oc = i % 18;
        float s = b_off[oc];
#pragma unroll
        for (int g2 = 0; g2 < 8; ++g2) s += red[g2][ps][oc];
        g_off[((size_t)n * 18 + oc) * HW + p0 + ps] = s;
    }
}

// ===========================================================================
// Deformable 3x3 conv on tensor cores (R13/R14-proven, unchanged).
// ===========================================================================
#define DPITCH 72
#define DSM_AS_H 0
#define DSM_AS_L 36864
#define DSM_BS_H 73728
#define DSM_BS_L 78336
#define DSM_BYTES 82944

__global__ __launch_bounds__(256, 2) void deform_mma_kernel(const float* __restrict__ b2) {
    extern __shared__ char dsm[];
    typedef __nv_bfloat16 (*tile_t)[DPITCH];
    tile_t As_h = (tile_t)(dsm + DSM_AS_H);
    tile_t As_l = (tile_t)(dsm + DSM_AS_L);
    tile_t Bs_h = (tile_t)(dsm + DSM_BS_H);
    tile_t Bs_l = (tile_t)(dsm + DSM_BS_L);

    const int pb = blockIdx.x * 32;
    const int n  = blockIdx.z;
    const int tid = threadIdx.x;
    const int wid = tid >> 5;
    const int lid = tid & 31;
    const int q = lid >> 2;
    const int r = lid & 3;

    const int gpx = tid & 31;
    const int gg  = tid >> 5;
    const int gcl = gg * 8;

    const float* fbase = g_r + (size_t)n * CB * HW;
    const float* offb  = g_off + (size_t)n * 18 * HW + pb + gpx;
    const int gh = (pb + gpx) / Ww;
    const int gw = (pb + gpx) % Ww;

    float acc[2][4][4] = {};

    int   idx0, idx1, idx2, idx3;
    float wt0, wt1, wt2, wt3;
#define BILIN(tap_) do {                                                       \
    float dy = offb[(size_t)((tap_) * 2 + 0) * HW];                            \
    float dx = offb[(size_t)((tap_) * 2 + 1) * HW];                            \
    float ys = (float)(gh + (tap_) / 3 - 1) + dy;                              \
    float xs = (float)(gw + (tap_) % 3 - 1) + dx;                              \
    float y0f = floorf(ys), x0f = floorf(xs);                                  \
    float wy1 = ys - y0f, wy0 = 1.f - wy1;                                     \
    float wx1 = xs - x0f, wx0 = 1.f - wx1;                                     \
    int y0 = (int)y0f, x0 = (int)x0f;                                          \
    int y1 = y0 + 1, x1 = x0 + 1;                                              \
    bool vy0 = (y0 >= 0) && (y0 < Hh);                                         \
    bool vy1 = (y1 >= 0) && (y1 < Hh);                                         \
    bool vx0 = (x0 >= 0) && (x0 < Ww);                                         \
    bool vx1 = (x1 >= 0) && (x1 < Ww);                                         \
    int yc0 = min(max(y0, 0), Hh - 1), yc1 = min(max(y1, 0), Hh - 1);          \
    int xc0 = min(max(x0, 0), Ww - 1), xc1 = min(max(x1, 0), Ww - 1);          \
    idx0 = yc0 * Ww + xc0;  wt0 = (vy0 && vx0) ? wy0 * wx0 : 0.f;              \
    idx1 = yc0 * Ww + xc1;  wt1 = (vy0 && vx1) ? wy0 * wx1 : 0.f;              \
    idx2 = yc1 * Ww + xc0;  wt2 = (vy1 && vx0) ? wy1 * wx0 : 0.f;              \
    idx3 = yc1 * Ww + xc1;  wt3 = (vy1 && vx1) ? wy1 * wx1 : 0.f;              \
} while (0)

    float v[8];
#define GATHER(c0_) do {                                                       \
    _Pragma("unroll")                                                          \
    for (int j = 0; j < 8; ++j) {                                              \
        const float* f = fbase + (size_t)((c0_) + gcl + j) * HW;               \
        v[j] = wt0 * __ldg(f + idx0) + wt1 * __ldg(f + idx1)                   \
             + wt2 * __ldg(f + idx2) + wt3 * __ldg(f + idx3);                  \
    }                                                                          \
} while (0)

    BILIN(0);
    GATHER(0);
    int tap_cur = 0;

    for (int ch = 0; ch < 36; ++ch) {
        const int tap = ch >> 2;
        const int k0  = tap * 256 + (ch & 3) * 64;
        __syncthreads();

#pragma unroll
        for (int pass = 0; pass < 8; ++pass) {
            int id   = tid + pass * 256;
            int row  = id >> 3;
            int col  = (id & 7) * 8;
            size_t goff = (size_t)row * KD + k0 + col;
            cp16((uint32_t)__cvta_generic_to_shared(&As_h[row][col]), g_w2h + goff);
            cp16((uint32_t)__cvta_generic_to_shared(&As_l[row][col]), g_w2l + goff);
        }
        CP_COMMIT();

        {
            uint4 h0, l0;
            split2(v[0], v[1], h0.x, l0.x);
            split2(v[2], v[3], h0.y, l0.y);
            split2(v[4], v[5], h0.z, l0.z);
            split2(v[6], v[7], h0.w, l0.w);
            *(uint4*)&Bs_h[gpx][gcl] = h0;
            *(uint4*)&Bs_l[gpx][gcl] = l0;
        }

        if (ch + 1 < 36) {
            int ntap = (ch + 1) >> 2;
            if (ntap != tap_cur) {
                BILIN(ntap);
                tap_cur = ntap;
            }
            GATHER(((ch + 1) & 3) * 64);
        }

        CP_WAIT0();
        __syncthreads();

#pragma unroll
        for (int ks = 0; ks < 64; ks += 16) {
            uint32_t bh[4][2], bl[4][2];
#pragma unroll
            for (int nf = 0; nf < 4; ++nf) {
                int nb = nf * 8;
                ldsm_x2(bh[nf], b_addr(Bs_h, nb, ks, lid));
                ldsm_x2(bl[nf], b_addr(Bs_l, nb, ks, lid));
            }
#pragma unroll
            for (int mf = 0; mf < 2; ++mf) {
                int mb = wid * 32 + mf * 16;
                uint32_t ah[4], al[4];
                ldsm_x4(ah, a_addr(As_h, mb, ks, lid));
                ldsm_x4(al, a_addr(As_l, mb, ks, lid));
#pragma unroll
                for (int nf = 0; nf < 4; ++nf) {
                    mma16816(acc[mf][nf], ah, bh[nf]);
                    mma16816(acc[mf][nf], ah, bl[nf]);
                    mma16816(acc[mf][nf], al, bh[nf]);
                }
            }
        }
    }

    // epilogue: bias + relu -> g_r2h/g_r2l (pre-split bf16 for conv3)
#pragma unroll
    for (int mf = 0; mf < 2; ++mf) {
#pragma unroll
        for (int half = 0; half < 2; ++half) {
            int o = wid * 32 + mf * 16 + q + half * 8;
            float bb = b2[o];
            size_t rowoff = ((size_t)n * CB + o) * HW + pb;
#pragma unroll
            for (int nf = 0; nf < 4; ++nf) {
                int px = nf * 8 + 2 * r;
                float c0 = fmaxf(acc[mf][nf][half * 2 + 0] + bb, 0.f);
                float c1 = fmaxf(acc[mf][nf][half * 2 + 1] + bb, 0.f);
                uint32_t hi, lo;
                split2(c0, c1, hi, lo);
                *(uint32_t*)&g_r2h[rowoff + px] = hi;
                *(uint32_t*)&g_r2l[rowoff + px] = lo;
            }
        }
    }
}

// ---------------------------------------------------------------------------
extern "C" void kernel_launch(void* const* d_in, const int* in_sizes, int n_in,
                              void* d_out, int out_size) {
    const float* x     = (const float*)d_in[0];
    const float* w1    = (const float*)d_in[1];
    const float* b1    = (const float*)d_in[2];
    const float* w_off = (const float*)d_in[3];
    const float* b_off = (const float*)d_in[4];
    const float* w2    = (const float*)d_in[5];
    const float* b2    = (const float*)d_in[6];
    const float* w3    = (const float*)d_in[7];
    const float* b3    = (const float*)d_in[8];
    float* out = (float*)d_out;

    float* r_ptr;
    cudaGetSymbolAddress((void**)&r_ptr, g_r);
    __nv_bfloat16 *w1h, *w1l, *w3h, *w3l, *r2h, *r2l;
    cudaGetSymbolAddress((void**)&w1h, g_w1h);
    cudaGetSymbolAddress((void**)&w1l, g_w1l);
    cudaGetSymbolAddress((void**)&w3h, g_w3h);
    cudaGetSymbolAddress((void**)&w3l, g_w3l);
    cudaGetSymbolAddress((void**)&r2h, g_r2h);
    cudaGetSymbolAddress((void**)&r2l, g_r2l);

    cudaFuncSetAttribute(deform_mma_kernel,
                         cudaFuncAttributeMaxDynamicSharedMemorySize, DSM_BYTES);
    cudaFuncSetAttribute(gemm_tc_kernel,
                         cudaFuncAttributeMaxDynamicSharedMemorySize, GSM_BYTES);
    cudaFuncSetAttribute(gemm_bf16b_kernel,
                         cudaFuncAttributeMaxDynamicSharedMemorySize, BBSM_BYTES);

    // weight preps
    prep_w2_kernel<<<(CB * KD + 255) / 256, 256>>>(w2);
    prep_w_kernel<<<(CB * CIN + 255) / 256, 256>>>(w1, w1h, w1l, CB * CIN);
    prep_w_kernel<<<(CIN * CB + 255) / 256, 256>>>(w3, w3h, w3l, CIN * CB);

    // conv1: 1024 -> 256, relu
    gemm_tc_kernel<<<dim3(HW / 64, CB / 128, Nn), 256, GSM_BYTES>>>(
        w1h, w1l, x, b1, nullptr, r_ptr, CB, CIN);

    // offset conv 3x3: 256 -> 18
    offset_conv_kernel<<<dim3(HW / 32, Nn), 256>>>(w_off, b_off);

    // deformable conv 3x3: 256 -> 256, relu (writes pre-split bf16)
    deform_mma_kernel<<<dim3(HW / 32, 1, Nn), 256, DSM_BYTES>>>(b2);

    // conv3: 256 -> 1024 + x residual, relu (all-bf16 GEMM)
    gemm_bf16b_kernel<<<dim3(HW / 64, CIN / 128, Nn), 256, BBSM_BYTES>>>(
        w3h, w3l, r2h, r2l, b3, x, out, CIN, CB);
}

// round 16
// speedup vs baseline: 1.2345x; 1.0469x over previous
#include <cuda_runtime.h>
#include <cuda_bf16.h>
#include <math.h>
#include <stdint.h>

#define Nn   4
#define CIN  1024
#define CB   256
#define Hh   56
#define Ww   56
#define HW   3136
#define KT   9
#define KD   (CB * KT)   // 2304

// Scratch (device globals: allocation-free rule)
__device__ float g_r  [Nn * CB * HW];     // conv1 output (relu)
__device__ float g_off[Nn * 2 * KT * HW]; // offset conv output
__device__ __nv_bfloat16 g_r2h[Nn * CB * HW]; // deform out, bf16 hi
__device__ __nv_bfloat16 g_r2l[Nn * CB * HW]; // deform out, bf16 lo
__device__ __nv_bfloat16 g_w2h[CB * KD];  // w2 split hi, [o][tap*256+c]
__device__ __nv_bfloat16 g_w2l[CB * KD];  // w2 split lo
__device__ __nv_bfloat16 g_w1h[CB * CIN]; // w1 split hi [256][1024]
__device__ __nv_bfloat16 g_w1l[CB * CIN];
__device__ __nv_bfloat16 g_w3h[CIN * CB]; // w3 split hi [1024][256]
__device__ __nv_bfloat16 g_w3l[CIN * CB];

// ---------------------------------------------------------------------------
// helpers
// ---------------------------------------------------------------------------
__device__ __forceinline__ void split2(float x, float y, uint32_t& hi, uint32_t& lo) {
    __nv_bfloat16 xh = __float2bfloat16(x);
    __nv_bfloat16 yh = __float2bfloat16(y);
    __nv_bfloat16 xl = __float2bfloat16(x - __bfloat162float(xh));
    __nv_bfloat16 yl = __float2bfloat16(y - __bfloat162float(yh));
    hi = ((uint32_t)__bfloat16_as_ushort(yh) << 16) | __bfloat16_as_ushort(xh);
    lo = ((uint32_t)__bfloat16_as_ushort(yl) << 16) | __bfloat16_as_ushort(xl);
}

__device__ __forceinline__ void mma16816(float* c, const uint32_t* a, const uint32_t* b) {
    asm volatile(
        "mma.sync.aligned.m16n8k16.row.col.f32.bf16.bf16.f32 "
        "{%0,%1,%2,%3}, {%4,%5,%6,%7}, {%8,%9}, {%0,%1,%2,%3};"
        : "+f"(c[0]), "+f"(c[1]), "+f"(c[2]), "+f"(c[3])
        : "r"(a[0]), "r"(a[1]), "r"(a[2]), "r"(a[3]), "r"(b[0]), "r"(b[1]));
}

__device__ __forceinline__ void ldsm_x4(uint32_t* r, uint32_t addr) {
    asm volatile("ldmatrix.sync.aligned.m8n8.x4.shared.b16 {%0,%1,%2,%3}, [%4];"
                 : "=r"(r[0]), "=r"(r[1]), "=r"(r[2]), "=r"(r[3]) : "r"(addr));
}
__device__ __forceinline__ void ldsm_x4t(uint32_t* r, uint32_t addr) {
    asm volatile("ldmatrix.sync.aligned.m8n8.x4.trans.shared.b16 {%0,%1,%2,%3}, [%4];"
                 : "=r"(r[0]), "=r"(r[1]), "=r"(r[2]), "=r"(r[3]) : "r"(addr));
}
template <int P>
__device__ __forceinline__ uint32_t a_addr(const __nv_bfloat16 (*S)[P], int mb, int ks, int ln) {
    int row = mb + (ln & 7) + ((ln >> 3) & 1) * 8;
    int col = ks + (ln >> 4) * 8;
    return (uint32_t)__cvta_generic_to_shared(&S[row][col]);
}
// non-trans x4 pair: B px-major [px][k]; regs {0,1}=frag at nb, {2,3}=frag at nb+8
template <int P>
__device__ __forceinline__ uint32_t b_addr4(const __nv_bfloat16 (*S)[P], int nb, int ks, int ln) {
    int row = nb + ((ln >> 4) << 3) + (ln & 7);
    int col = ks + ((ln >> 3) & 1) * 8;
    return (uint32_t)__cvta_generic_to_shared(&S[row][col]);
}
// trans x4 pair: B k-major [k][px]; lanes 0-15 rows ks..ks+15 @nb, 16-31 @nb+8
template <int P>
__device__ __forceinline__ uint32_t b_addr4t(const __nv_bfloat16 (*S)[P], int nb, int ks, int ln) {
    int row = ks + (ln & 15);
    int col = nb + ((ln >> 4) << 3);
    return (uint32_t)__cvta_generic_to_shared(&S[row][col]);
}
__device__ __forceinline__ void cp16(uint32_t saddr, const void* g) {
    asm volatile("cp.async.ca.shared.global [%0], [%1], 16;"
                 :: "r"(saddr), "l"(g) : "memory");
}
#define CP_COMMIT() asm volatile("cp.async.commit_group;" ::: "memory")
#define CP_WAIT0()  asm volatile("cp.async.wait_group 0;" ::: "memory")
#define CP_WAIT1()  asm volatile("cp.async.wait_group 1;" ::: "memory")

// ---------------------------------------------------------------------------
// weight prep: fp32 -> bf16 hi/lo
// ---------------------------------------------------------------------------
__global__ void prep_w2_kernel(const float* __restrict__ w2) {
    int i = blockIdx.x * 256 + threadIdx.x;
    if (i < CB * KD) {
        int o = i / KD;
        int k = i % KD;
        int tap = k >> 8;
        int c   = k & 255;
        float v = w2[(o * CB + c) * KT + tap];
        __nv_bfloat16 h = __float2bfloat16(v);
        g_w2h[i] = h;
        g_w2l[i] = __float2bfloat16(v - __bfloat162float(h));
    }
}
__global__ void prep_w_kernel(const float* __restrict__ w,
                              __nv_bfloat16* __restrict__ oh,
                              __nv_bfloat16* __restrict__ ol, int total) {
    int i = blockIdx.x * 256 + threadIdx.x;
    if (i < total) {
        float v = w[i];
        __nv_bfloat16 h = __float2bfloat16(v);
        oh[i] = h;
        ol[i] = __float2bfloat16(v - __bfloat162float(h));
    }
}

// ===========================================================================
// Tensor-core GEMM for conv1: A pre-split bf16 via cp.async double buffer;
// B fp32 -> k-major smem (conflict-free STS.64), ldmatrix x4 trans frags.
// ===========================================================================
#define GKP 72
#define G_AS_BYTES (128 * GKP * 2)
#define G_STAGE    (2 * G_AS_BYTES)
#define G_B_OFF    (2 * G_STAGE)
#define G_BS_BYTES (64 * GKP * 2)
#define GSM_BYTES  (G_B_OFF + 2 * G_BS_BYTES)

__global__ __launch_bounds__(256) void gemm_tc_kernel(
        const __nv_bfloat16* __restrict__ Ah,
        const __nv_bfloat16* __restrict__ Al,
        const float* __restrict__ Bx,
        const float* __restrict__ bias, const float* __restrict__ resid,
        float* __restrict__ C, int M, int Kd) {
    extern __shared__ char gsm[];
    typedef __nv_bfloat16 (*tile_t)[GKP];
    tile_t Bs_h = (tile_t)(gsm + G_B_OFF);
    tile_t Bs_l = (tile_t)(gsm + G_B_OFF + G_BS_BYTES);

    const int n  = blockIdx.z;
    const int m0 = blockIdx.y * 128;
    const int p0 = blockIdx.x * 64;
    const int tid = threadIdx.x;
    const int wid = tid >> 5;
    const int lid = tid & 31;
    const int q = lid >> 2;
    const int r = lid & 3;
    const int wm = wid & 3;
    const int wn = wid >> 2;
    const float* Bn = Bx + (size_t)n * Kd * HW;

    const int b_px = (tid & 15) * 4;
    const int b_kp = (tid >> 4) * 2;

    float acc[2][4][4] = {};
    const int KC = Kd >> 6;

#define STAGE_A(s_, k0_) do {                                                  \
    tile_t _ah = (tile_t)(gsm + (s_) * G_STAGE);                               \
    tile_t _al = (tile_t)(gsm + (s_) * G_STAGE + G_AS_BYTES);                  \
    _Pragma("unroll")                                                          \
    for (int pass = 0; pass < 4; ++pass) {                                     \
        int id  = tid + pass * 256;                                            \
        int row = id >> 3;                                                     \
        int col = (id & 7) * 8;                                                \
        size_t goff = (size_t)(m0 + row) * Kd + (k0_) + col;                   \
        cp16((uint32_t)__cvta_generic_to_shared(&_ah[row][col]), Ah + goff);   \
        cp16((uint32_t)__cvta_generic_to_shared(&_al[row][col]), Al + goff);   \
    }                                                                          \
    CP_COMMIT();                                                               \
} while (0)

    float4 vk[2][2];
#define LOAD_B(k0_) do {                                                       \
    _Pragma("unroll")                                                          \
    for (int p = 0; p < 2; ++p) {                                              \
        const float* gB = Bn + (size_t)((k0_) + b_kp + p * 32) * HW + p0 + b_px; \
        vk[p][0] = *(const float4*)gB;                                         \
        vk[p][1] = *(const float4*)(gB + HW);                                  \
    }                                                                          \
} while (0)

#define STORE_B() do {                                                         \
    _Pragma("unroll")                                                          \
    for (int p = 0; p < 2; ++p) {                                              \
        _Pragma("unroll")                                                      \
        for (int rr = 0; rr < 2; ++rr) {                                       \
            float4 vv = vk[p][rr];                                             \
            uint32_t h0, l0, h1, l1;                                           \
            split2(vv.x, vv.y, h0, l0);                                        \
            split2(vv.z, vv.w, h1, l1);                                        \
            int kk = b_kp + p * 32 + rr;                                       \
            *(uint2*)&Bs_h[kk][b_px] = make_uint2(h0, h1);                     \
            *(uint2*)&Bs_l[kk][b_px] = make_uint2(l0, l1);                     \
        }                                                                      \
    }                                                                          \
} while (0)

    STAGE_A(0, 0);
    LOAD_B(0);

    for (int kc = 0; kc < KC; ++kc) {
        const int s = kc & 1;
        __syncthreads();
        STORE_B();
        if (kc + 1 < KC) {
            STAGE_A(s ^ 1, (kc + 1) << 6);
            LOAD_B((kc + 1) << 6);
            CP_WAIT1();
        } else {
            CP_WAIT0();
        }
        __syncthreads();

        tile_t ash = (tile_t)(gsm + s * G_STAGE);
        tile_t asl = (tile_t)(gsm + s * G_STAGE + G_AS_BYTES);
#pragma unroll
        for (int ks = 0; ks < 64; ks += 16) {
            uint32_t bh[8], bl[8];   // frag nf at bh+2*nf
            ldsm_x4t(bh,     b_addr4t(Bs_h, wn * 32,      ks, lid));
            ldsm_x4t(bh + 4, b_addr4t(Bs_h, wn * 32 + 16, ks, lid));
            ldsm_x4t(bl,     b_addr4t(Bs_l, wn * 32,      ks, lid));
            ldsm_x4t(bl + 4, b_addr4t(Bs_l, wn * 32 + 16, ks, lid));
#pragma unroll
            for (int mf = 0; mf < 2; ++mf) {
                int mb = wm * 32 + mf * 16;
                uint32_t ah[4], al[4];
                ldsm_x4(ah, a_addr(ash, mb, ks, lid));
                ldsm_x4(al, a_addr(asl, mb, ks, lid));
#pragma unroll
                for (int nf = 0; nf < 4; ++nf) {
                    mma16816(acc[mf][nf], ah, bh + nf * 2);
                    mma16816(acc[mf][nf], ah, bl + nf * 2);
                    mma16816(acc[mf][nf], al, bh + nf * 2);
                }
            }
        }
    }

#pragma unroll
    for (int mf = 0; mf < 2; ++mf) {
#pragma unroll
        for (int half = 0; half < 2; ++half) {
            int mm = m0 + wm * 32 + mf * 16 + q + half * 8;
            float bb = bias[mm];
#pragma unroll
            for (int nf = 0; nf < 4; ++nf) {
                int px = p0 + wn * 32 + nf * 8 + 2 * r;
                float c0 = acc[mf][nf][half * 2 + 0];
                float c1 = acc[mf][nf][half * 2 + 1];
                size_t base = ((size_t)n * M + mm) * HW + px;
                if (resid) {
                    float2 rv = *(const float2*)(resid + base);
                    c0 += rv.x;
                    c1 += rv.y;
                }
                float2 o;
                o.x = fmaxf(c0 + bb, 0.f);
                o.y = fmaxf(c1 + bb, 0.f);
                *(float2*)(C + base) = o;
            }
        }
    }
}

// ===========================================================================
// conv3 GEMM: A AND B pre-split bf16 (R14-proven); B frags via x4 trans.
// ===========================================================================
#define BB_A_TILE (128 * GKP * 2)
#define BB_A_STAGE (2 * BB_A_TILE)
#define BB_B_OFF   (2 * BB_A_STAGE)
#define BB_B_TILE  (64 * GKP * 2)
#define BB_B_STAGE (2 * BB_B_TILE)
#define BBSM_BYTES (BB_B_OFF + 2 * BB_B_STAGE)

__global__ __launch_bounds__(256) void gemm_bf16b_kernel(
        const __nv_bfloat16* __restrict__ Ah,
        const __nv_bfloat16* __restrict__ Al,
        const __nv_bfloat16* __restrict__ Bh,
        const __nv_bfloat16* __restrict__ Bl,
        const float* __restrict__ bias, const float* __restrict__ resid,
        float* __restrict__ C, int M, int Kd) {
    extern __shared__ char gsm[];
    typedef __nv_bfloat16 (*tile_t)[GKP];

    const int n  = blockIdx.z;
    const int m0 = blockIdx.y * 128;
    const int p0 = blockIdx.x * 64;
    const int tid = threadIdx.x;
    const int wid = tid >> 5;
    const int lid = tid & 31;
    const int q = lid >> 2;
    const int r = lid & 3;
    const int wm = wid & 3;
    const int wn = wid >> 2;

    float acc[2][4][4] = {};
    const int KC = Kd >> 6;

#define STAGE_AB(s_, k0_) do {                                                 \
    tile_t _ah = (tile_t)(gsm + (s_) * BB_A_STAGE);                            \
    tile_t _al = (tile_t)(gsm + (s_) * BB_A_STAGE + BB_A_TILE);                \
    tile_t _bh = (tile_t)(gsm + BB_B_OFF + (s_) * BB_B_STAGE);                 \
    tile_t _bl = (tile_t)(gsm + BB_B_OFF + (s_) * BB_B_STAGE + BB_B_TILE);     \
    _Pragma("unroll")                                                          \
    for (int pass = 0; pass < 4; ++pass) {                                     \
        int id  = tid + pass * 256;                                            \
        int row = id >> 3;                                                     \
        int col = (id & 7) * 8;                                                \
        size_t goff = (size_t)(m0 + row) * Kd + (k0_) + col;                   \
        cp16((uint32_t)__cvta_generic_to_shared(&_ah[row][col]), Ah + goff);   \
        cp16((uint32_t)__cvta_generic_to_shared(&_al[row][col]), Al + goff);   \
    }                                                                          \
    _Pragma("unroll")                                                          \
    for (int pass = 0; pass < 2; ++pass) {                                     \
        int id  = tid + pass * 256;                                            \
        int row = id >> 3;                                                     \
        int col = (id & 7) * 8;                                                \
        size_t goff = ((size_t)n * Kd + (k0_) + row) * HW + p0 + col;          \
        cp16((uint32_t)__cvta_generic_to_shared(&_bh[row][col]), Bh + goff);   \
        cp16((uint32_t)__cvta_generic_to_shared(&_bl[row][col]), Bl + goff);   \
    }                                                                          \
    CP_COMMIT();                                                               \
} while (0)

    STAGE_AB(0, 0);

    for (int kc = 0; kc < KC; ++kc) {
        const int s = kc & 1;
        __syncthreads();
        if (kc + 1 < KC) {
            STAGE_AB(s ^ 1, (kc + 1) << 6);
            CP_WAIT1();
        } else {
            CP_WAIT0();
        }
        __syncthreads();

        tile_t ash = (tile_t)(gsm + s * BB_A_STAGE);
        tile_t asl = (tile_t)(gsm + s * BB_A_STAGE + BB_A_TILE);
        tile_t bsh = (tile_t)(gsm + BB_B_OFF + s * BB_B_STAGE);
        tile_t bsl = (tile_t)(gsm + BB_B_OFF + s * BB_B_STAGE + BB_B_TILE);
#pragma unroll
        for (int ks = 0; ks < 64; ks += 16) {
            uint32_t bh[8], bl[8];
            ldsm_x4t(bh,     b_addr4t(bsh, wn * 32,      ks, lid));
            ldsm_x4t(bh + 4, b_addr4t(bsh, wn * 32 + 16, ks, lid));
            ldsm_x4t(bl,     b_addr4t(bsl, wn * 32,      ks, lid));
            ldsm_x4t(bl + 4, b_addr4t(bsl, wn * 32 + 16, ks, lid));
#pragma unroll
            for (int mf = 0; mf < 2; ++mf) {
                int mb = wm * 32 + mf * 16;
                uint32_t ah[4], al[4];
                ldsm_x4(ah, a_addr(ash, mb, ks, lid));
                ldsm_x4(al, a_addr(asl, mb, ks, lid));
#pragma unroll
                for (int nf = 0; nf < 4; ++nf) {
                    mma16816(acc[mf][nf], ah, bh + nf * 2);
                    mma16816(acc[mf][nf], ah, bl + nf * 2);
                    mma16816(acc[mf][nf], al, bh + nf * 2);
                }
            }
        }
    }

#pragma unroll
    for (int mf = 0; mf < 2; ++mf) {
#pragma unroll
        for (int half = 0; half < 2; ++half) {
            int mm = m0 + wm * 32 + mf * 16 + q + half * 8;
            float bb = bias[mm];
#pragma unroll
            for (int nf = 0; nf < 4; ++nf) {
                int px = p0 + wn * 32 + nf * 8 + 2 * r;
                float c0 = acc[mf][nf][half * 2 + 0];
                float c1 = acc[mf][nf][half * 2 + 1];
                size_t base = ((size_t)n * M + mm) * HW + px;
                float2 rv = *(const float2*)(resid + base);
                c0 += rv.x;
                c1 += rv.y;
                float2 o;
                o.x = fmaxf(c0 + bb, 0.f);
                o.y = fmaxf(c1 + bb, 0.f);
                *(float2*)(C + base) = o;
            }
        }
    }
}

// ---------------------------------------------------------------------------
// Offset conv: 3x3 SAME, CB=256 -> 18 ch. 32 px/block (R9 version).
// ---------------------------------------------------------------------------
__global__ __launch_bounds__(256) void offset_conv_kernel(
        const float* __restrict__ w_off, const float* __restrict__ b_off) {
    __shared__ float red[8][32][18];
    const int n  = blockIdx.y;
    const int p0 = blockIdx.x * 32;
    const int tid = threadIdx.x;
    const int g  = tid >> 5;
    const int lx = tid & 31;

    float acc[18];
#pragma unroll
    for (int oc = 0; oc < 18; ++oc) acc[oc] = 0.f;

    const int p = p0 + lx;
    const int h = p / Ww, w = p % Ww;

    for (int ci = g; ci < CB; ci += 8) {
        const float* rb = g_r + ((size_t)n * CB + ci) * HW;
        float v[9];
#pragma unroll
        for (int t = 0; t < 9; ++t) {
            int y = h + t / 3 - 1;
            int x = w + t % 3 - 1;
            v[t] = (y >= 0 && y < Hh && x >= 0 && x < Ww) ? __ldg(rb + y * Ww + x) : 0.f;
        }
        const float* wb = w_off + ci * 9;
#pragma unroll
        for (int oc = 0; oc < 18; ++oc) {
#pragma unroll
            for (int t = 0; t < 9; ++t)
                acc[oc] += __ldg(wb + oc * (CB * 9) + t) * v[t];
        }
    }

#pragma unroll
    for (int oc = 0; oc < 18; ++oc)
        red[g][lx][oc] = acc[oc];
    __syncthreads();

    for (int i = tid; i < 32 * 18; i += 256) {
        int ps = i / 18, oc = i % 18;
        float s = b_off[oc];
#pragma unroll
        for (int g2 = 0; g2 < 8; ++g2) s += red[g2][ps][oc];
        g_off[((size_t)n * 18 + oc) * HW + p0 + ps] = s;
    }
}

// ===========================================================================
// Deformable 3x3 conv on tensor cores (R13/R14-proven); B frags via x4 pairs.
// ===========================================================================
#define DPITCH 72
#define DSM_AS_H 0
#define DSM_AS_L 36864
#define DSM_BS_H 73728
#define DSM_BS_L 78336
#define DSM_BYTES 82944

__global__ __launch_bounds__(256, 2) void deform_mma_kernel(const float* __restrict__ b2) {
    extern __shared__ char dsm[];
    typedef __nv_bfloat16 (*tile_t)[DPITCH];
    tile_t As_h = (tile_t)(dsm + DSM_AS_H);
    tile_t As_l = (tile_t)(dsm + DSM_AS_L);
    tile_t Bs_h = (tile_t)(dsm + DSM_BS_H);
    tile_t Bs_l = (tile_t)(dsm + DSM_BS_L);

    const int pb = blockIdx.x * 32;
    const int n  = blockIdx.z;
    const int tid = threadIdx.x;
    const int wid = tid >> 5;
    const int lid = tid & 31;
    const int q = lid >> 2;
    const int r = lid & 3;

    const int gpx = tid & 31;
    const int gg  = tid >> 5;
    const int gcl = gg * 8;

    const float* fbase = g_r + (size_t)n * CB * HW;
    const float* offb  = g_off + (size_t)n * 18 * HW + pb + gpx;
    const int gh = (pb + gpx) / Ww;
    const int gw = (pb + gpx) % Ww;

    float acc[2][4][4] = {};

    int   idx0, idx1, idx2, idx3;
    float wt0, wt1, wt2, wt3;
#define BILIN(tap_) do {                                                       \
    float dy = offb[(size_t)((tap_) * 2 + 0) * HW];                            \
    float dx = offb[(size_t)((tap_) * 2 + 1) * HW];                            \
    float ys = (float)(gh + (tap_) / 3 - 1) + dy;                              \
    float xs = (float)(gw + (tap_) % 3 - 1) + dx;                              \
    float y0f = floorf(ys), x0f = floorf(xs);                                  \
    float wy1 = ys - y0f, wy0 = 1.f - wy1;                                     \
    float wx1 = xs - x0f, wx0 = 1.f - wx1;                                     \
    int y0 = (int)y0f, x0 = (int)x0f;                                          \
    int y1 = y0 + 1, x1 = x0 + 1;                                              \
    bool vy0 = (y0 >= 0) && (y0 < Hh);                                         \
    bool vy1 = (y1 >= 0) && (y1 < Hh);                                         \
    bool vx0 = (x0 >= 0) && (x0 < Ww);                                         \
    bool vx1 = (x1 >= 0) && (x1 < Ww);                                         \
    int yc0 = min(max(y0, 0), Hh - 1), yc1 = min(max(y1, 0), Hh - 1);          \
    int xc0 = min(max(x0, 0), Ww - 1), xc1 = min(max(x1, 0), Ww - 1);          \
    idx0 = yc0 * Ww + xc0;  wt0 = (vy0 && vx0) ? wy0 * wx0 : 0.f;              \
    idx1 = yc0 * Ww + xc1;  wt1 = (vy0 && vx1) ? wy0 * wx1 : 0.f;              \
    idx2 = yc1 * Ww + xc0;  wt2 = (vy1 && vx0) ? wy1 * wx0 : 0.f;              \
    idx3 = yc1 * Ww + xc1;  wt3 = (vy1 && vx1) ? wy1 * wx1 : 0.f;              \
} while (0)

    float v[8];
#define GATHER(c0_) do {                                                       \
    _Pragma("unroll")                                                          \
    for (int j = 0; j < 8; ++j) {                                              \
        const float* f = fbase + (size_t)((c0_) + gcl + j) * HW;               \
        v[j] = wt0 * __ldg(f + idx0) + wt1 * __ldg(f + idx1)                   \
             + wt2 * __ldg(f + idx2) + wt3 * __ldg(f + idx3);                  \
    }                                                                          \
} while (0)

    BILIN(0);
    GATHER(0);
    int tap_cur = 0;

    for (int ch = 0; ch < 36; ++ch) {
        const int tap = ch >> 2;
        const int k0  = tap * 256 + (ch & 3) * 64;
        __syncthreads();

#pragma unroll
        for (int pass = 0; pass < 8; ++pass) {
            int id   = tid + pass * 256;
            int row  = id >> 3;
            int col  = (id & 7) * 8;
            size_t goff = (size_t)row * KD + k0 + col;
            cp16((uint32_t)__cvta_generic_to_shared(&As_h[row][col]), g_w2h + goff);
            cp16((uint32_t)__cvta_generic_to_shared(&As_l[row][col]), g_w2l + goff);
        }
        CP_COMMIT();

        {
            uint4 h0, l0;
            split2(v[0], v[1], h0.x, l0.x);
            split2(v[2], v[3], h0.y, l0.y);
            split2(v[4], v[5], h0.z, l0.z);
            split2(v[6], v[7], h0.w, l0.w);
            *(uint4*)&Bs_h[gpx][gcl] = h0;
            *(uint4*)&Bs_l[gpx][gcl] = l0;
        }

        if (ch + 1 < 36) {
            int ntap = (ch + 1) >> 2;
            if (ntap != tap_cur) {
                BILIN(ntap);
                tap_cur = ntap;
            }
            GATHER(((ch + 1) & 3) * 64);
        }

        CP_WAIT0();
        __syncthreads();

#pragma unroll
        for (int ks = 0; ks < 64; ks += 16) {
            uint32_t bh[8], bl[8];   // frag nf at +2*nf
            ldsm_x4(bh,     b_addr4(Bs_h, 0,  ks, lid));
            ldsm_x4(bh + 4, b_addr4(Bs_h, 16, ks, lid));
            ldsm_x4(bl,     b_addr4(Bs_l, 0,  ks, lid));
            ldsm_x4(bl + 4, b_addr4(Bs_l, 16, ks, lid));
#pragma unroll
            for (int mf = 0; mf < 2; ++mf) {
                int mb = wid * 32 + mf * 16;
                uint32_t ah[4], al[4];
                ldsm_x4(ah, a_addr(As_h, mb, ks, lid));
                ldsm_x4(al, a_addr(As_l, mb, ks, lid));
#pragma unroll
                for (int nf = 0; nf < 4; ++nf) {
                    mma16816(acc[mf][nf], ah, bh + nf * 2);
                    mma16816(acc[mf][nf], ah, bl + nf * 2);
                    mma16816(acc[mf][nf], al, bh + nf * 2);
                }
            }
        }
    }

    // epilogue: bias + relu -> g_r2h/g_r2l (pre-split bf16 for conv3)
#pragma unroll
    for (int mf = 0; mf < 2; ++mf) {
#pragma unroll
        for (int half = 0; half < 2; ++half) {
            int o = wid * 32 + mf * 16 + q + half * 8;
            float bb = b2[o];
            size_t rowoff = ((size_t)n * CB + o) * HW + pb;
#pragma unroll
            for (int nf = 0; nf < 4; ++nf) {
                int px = nf * 8 + 2 * r;
                float c0 = fmaxf(acc[mf][nf][half * 2 + 0] + bb, 0.f);
                float c1 = fmaxf(acc[mf][nf][half * 2 + 1] + bb, 0.f);
                uint32_t hi, lo;
                split2(c0, c1, hi, lo);
                *(uint32_t*)&g_r2h[rowoff + px] = hi;
                *(uint32_t*)&g_r2l[rowoff + px] = lo;
            }
        }
    }
}

// ---------------------------------------------------------------------------
extern "C" void kernel_launch(void* const* d_in, const int* in_sizes, int n_in,
                              void* d_out, int out_size) {
    const float* x     = (const float*)d_in[0];
    const float* w1    = (const float*)d_in[1];
    const float* b1    = (const float*)d_in[2];
    const float* w_off = (const float*)d_in[3];
    const float* b_off = (const float*)d_in[4];
    const float* w2    = (const float*)d_in[5];
    const float* b2    = (const float*)d_in[6];
    const float* w3    = (const float*)d_in[7];
    const float* b3    = (const float*)d_in[8];
    float* out = (float*)d_out;

    float* r_ptr;
    cudaGetSymbolAddress((void**)&r_ptr, g_r);
    __nv_bfloat16 *w1h, *w1l, *w3h, *w3l, *r2h, *r2l;
    cudaGetSymbolAddress((void**)&w1h, g_w1h);
    cudaGetSymbolAddress((void**)&w1l, g_w1l);
    cudaGetSymbolAddress((void**)&w3h, g_w3h);
    cudaGetSymbolAddress((void**)&w3l, g_w3l);
    cudaGetSymbolAddress((void**)&r2h, g_r2h);
    cudaGetSymbolAddress((void**)&r2l, g_r2l);

    cudaFuncSetAttribute(deform_mma_kernel,
                         cudaFuncAttributeMaxDynamicSharedMemorySize, DSM_BYTES);
    cudaFuncSetAttribute(gemm_tc_kernel,
                         cudaFuncAttributeMaxDynamicSharedMemorySize, GSM_BYTES);
    cudaFuncSetAttribute(gemm_bf16b_kernel,
                         cudaFuncAttributeMaxDynamicSharedMemorySize, BBSM_BYTES);

    // weight preps
    prep_w2_kernel<<<(CB * KD + 255) / 256, 256>>>(w2);
    prep_w_kernel<<<(CB * CIN + 255) / 256, 256>>>(w1, w1h, w1l, CB * CIN);
    prep_w_kernel<<<(CIN * CB + 255) / 256, 256>>>(w3, w3h, w3l, CIN * CB);

    // conv1: 1024 -> 256, relu
    gemm_tc_kernel<<<dim3(HW / 64, CB / 128, Nn), 256, GSM_BYTES>>>(
        w1h, w1l, x, b1, nullptr, r_ptr, CB, CIN);

    // offset conv 3x3: 256 -> 18
    offset_conv_kernel<<<dim3(HW / 32, Nn), 256>>>(w_off, b_off);

    // deformable conv 3x3: 256 -> 256, relu (writes pre-split bf16)
    deform_mma_kernel<<<dim3(HW / 32, 1, Nn), 256, DSM_BYTES>>>(b2);

    // conv3: 256 -> 1024 + x residual, relu (all-bf16 GEMM)
    gemm_bf16b_kernel<<<dim3(HW / 64, CIN / 128, Nn), 256, BBSM_BYTES>>>(
        w3h, w3l, r2h, r2l, b3, x, out, CIN, CB);
}